// round 7
// baseline (speedup 1.0000x reference)
#include <cuda_runtime.h>
#include <cuda_fp16.h>
#include <cstdint>

#define QN   10000
#define NCAM 6
#define DIM  256
#define HWF  2816     // 32*88
#define NH   8
#define HD   32
#define HFv  32
#define WFv  88
#define MROWS (NCAM*QN)   // 60000
#define OAC  192          // 128 offsets + 64 attn logits

// ---------------- scratch ----------------
__device__ __half d_value[NCAM*NH*HWF*HD];  // (cam, head, hw, hd) fp16
__device__ float d_offattn[(size_t)MROWS*OAC];
__device__ float d_S[(size_t)QN*DIM];
__device__ float d_gflag[QN];
__device__ float d_bias2[NCAM*DIM];
__device__ float d_Wc[DIM*DIM];             // W_out @ W_inner
__device__ float d_bi2[DIM];                // W_out @ b_inner
__device__ int   d_mask_mode;               // 0=u8, 1=i32, 2=f32

__device__ __forceinline__ int mask_elem(const void* mask, size_t idx, int mode) {
    if (mode == 0) return ((const unsigned char*)mask)[idx] != 0;
    if (mode == 1) return ((const int*)mask)[idx] != 0;
    return ((const float*)mask)[idx] != 0.f;
}

// ---------------- prep A: bias2 (blocks 0..5) + mask detect (block 6) ----------------
__global__ void prep_a(const float* __restrict__ lvl, const float* __restrict__ camemb,
                       const float* __restrict__ Wv, const float* __restrict__ bv,
                       const unsigned int* __restrict__ mk) {
    int c = blockIdx.x, j = threadIdx.x;
    if (c == NCAM) {
        if (j < 32) {
            bool f = false, multi = false;
            for (int i = j; i < 256; i += 32) {
                unsigned int w = mk[i];
                f |= (w == 0x3F800000u);
                multi |= (w != 0x3F800000u && w > 1u);
            }
            unsigned bf = __ballot_sync(0xffffffffu, f), bm = __ballot_sync(0xffffffffu, multi);
            if (j == 0) d_mask_mode = bf ? 2 : (bm ? 0 : 1);
        }
        return;
    }
    __shared__ float e[DIM];
    e[j] = lvl[j] + camemb[c*DIM + j];
    __syncthreads();
    const float4* w4 = (const float4*)(Wv + (size_t)j*DIM);
    const float4* e4 = (const float4*)e;
    float s = bv[j];
    #pragma unroll 8
    for (int k = 0; k < DIM/4; k++) {
        float4 w = w4[k]; float4 ev = e4[k];
        s += w.x*ev.x + w.y*ev.y + w.z*ev.z + w.w*ev.w;
    }
    d_bias2[c*DIM + j] = s;
}

// ---------------- prep B: Wc (blocks 0..255) + bi2 (block 256) ----------------
__global__ void prep_b(const float* __restrict__ Wo, const float* __restrict__ Wi,
                       const float* __restrict__ bi) {
    int i = blockIdx.x, j = threadIdx.x;
    if (i == DIM) {
        int w = j >> 5, l = j & 31;
        for (int ii = w; ii < DIM; ii += 8) {
            float s = 0.f;
            #pragma unroll
            for (int t = 0; t < 8; t++) {
                int k = l + 32*t;
                s += Wo[(size_t)ii*DIM + k] * bi[k];
            }
            #pragma unroll
            for (int o = 16; o; o >>= 1) s += __shfl_xor_sync(0xffffffffu, s, o);
            if (l == 0) d_bi2[ii] = s;
        }
        return;
    }
    __shared__ float wo[DIM];
    wo[j] = Wo[(size_t)i*DIM + j];
    __syncthreads();
    float s = 0.f;
    #pragma unroll 8
    for (int k = 0; k < DIM; k++) s += wo[k] * Wi[(size_t)k*DIM + j];
    d_Wc[(size_t)i*DIM + j] = s;
}

// ---------------- tf32 mma.sync GEMM core (ldmatrix operand fetch) ----------------
#define ASTR 20
#define ASTR1 136
#define BSTR 20

__device__ __forceinline__ unsigned f2tf(float f) {
    unsigned u; asm("cvt.rna.tf32.f32 %0, %1;" : "=r"(u) : "f"(f)); return u;
}
__device__ __forceinline__ void mma1688(float* c, const unsigned* a, const unsigned* b) {
    asm volatile("mma.sync.aligned.m16n8k8.row.col.f32.tf32.tf32.f32 "
        "{%0,%1,%2,%3}, {%4,%5,%6,%7}, {%8,%9}, {%0,%1,%2,%3};"
        : "+f"(c[0]), "+f"(c[1]), "+f"(c[2]), "+f"(c[3])
        : "r"(a[0]), "r"(a[1]), "r"(a[2]), "r"(a[3]), "r"(b[0]), "r"(b[1]));
}
__device__ __forceinline__ uint4 tf4(float4 v) {
    return make_uint4(f2tf(v.x), f2tf(v.y), f2tf(v.z), f2tf(v.w));
}
__device__ __forceinline__ void ldmx4(unsigned* r, unsigned addr) {
    asm volatile("ldmatrix.sync.aligned.m8n8.x4.shared.b16 {%0,%1,%2,%3}, [%4];"
        : "=r"(r[0]), "=r"(r[1]), "=r"(r[2]), "=r"(r[3]) : "r"(addr));
}
__device__ __forceinline__ unsigned smem_addr(const void* p) {
    return (unsigned)__cvta_generic_to_shared(p);
}

template<int MODE>
__global__ __launch_bounds__(256, 2) void gemm_tc(
    const float* __restrict__ A0, const float* __restrict__ A1,
    const float* __restrict__ B0, const float* __restrict__ B1,
    const float* __restrict__ bias0, const float* __restrict__ bias1,
    float* __restrict__ C)
{
    __shared__ unsigned As[2][2560];
    __shared__ unsigned Bs[2][1280];
    const int tid = threadIdx.x;
    const int lane = tid & 31, wid = tid >> 5;
    const int mw = (wid & 3) * 32, nw = (wid >> 2) * 32;
    const int g = lane >> 2, t = lane & 3;
    const int j0 = blockIdx.x * 64;

    int camI = 0, p0 = 0, m0 = 0;
    if (MODE == 1) { camI = blockIdx.y / 22; p0 = (blockIdx.y % 22) * 128; }
    else m0 = blockIdx.y * 128;
    const int Mrows = (MODE == 2) ? MROWS : QN;

    const float* Aptr = (MODE == 3) ? (const float*)d_S : A0;
    const int bn_ = tid >> 2, bkq = (tid & 3) * 4;
    const int jg = j0 + bn_;
    const float* wrow;
    if (MODE == 2) wrow = (jg < 128) ? (B0 + (size_t)jg*DIM) : (B1 + (size_t)(jg-128)*DIM);
    else if (MODE == 3) wrow = (const float*)d_Wc + (size_t)jg*DIM;
    else wrow = B0 + (size_t)jg*DIM;

    const int am = tid >> 1, akq = (tid & 1) * 8;       // MODE 2/3 A staging
    const int kk = tid >> 4, pg = tid & 15;             // MODE 1 A staging
    const int mga = m0 + am;

    const unsigned as_base = smem_addr(&As[0][0]);
    const unsigned bs_base = smem_addr(&Bs[0][0]);
    const int arow = mw + (lane & 7) + ((lane >> 3) & 1) * 8;
    const int acol = ((lane >> 4) & 1) * 4;
    const int brow = nw + (lane & 7) + ((lane >> 4) & 1) * 8;
    const int bcol = ((lane >> 3) & 1) * 4;

    float c_[2][4][4];
    #pragma unroll
    for (int mi = 0; mi < 2; mi++)
        #pragma unroll
        for (int ni = 0; ni < 4; ni++)
            #pragma unroll
            for (int r = 0; r < 4; r++) c_[mi][ni][r] = 0.f;

    float4 pa0, pa1, pb;
    auto zero4 = make_float4(0.f, 0.f, 0.f, 0.f);
    #define LOAD_CHUNK(k0) do {                                                      \
        if (MODE == 1) {                                                             \
            const float* src = A0 + ((size_t)(camI*DIM + (k0) + kk))*HWF + p0 + pg*8;\
            pa0 = *(const float4*)src; pa1 = *(const float4*)(src + 4);              \
        } else {                                                                     \
            pa0 = zero4; pa1 = zero4;                                                \
            if (mga < Mrows) {                                                       \
                pa0 = *(const float4*)(Aptr + (size_t)mga*DIM + (k0) + akq);         \
                pa1 = *(const float4*)(Aptr + (size_t)mga*DIM + (k0) + akq + 4);     \
                if (MODE == 2) {                                                     \
                    float4 q0 = *(const float4*)(A1 + (size_t)mga*DIM + (k0) + akq); \
                    float4 q1 = *(const float4*)(A1 + (size_t)mga*DIM + (k0) + akq+4);\
                    pa0.x+=q0.x; pa0.y+=q0.y; pa0.z+=q0.z; pa0.w+=q0.w;              \
                    pa1.x+=q1.x; pa1.y+=q1.y; pa1.z+=q1.z; pa1.w+=q1.w;              \
                }                                                                    \
            }                                                                        \
        }                                                                            \
        pb = *(const float4*)(wrow + (k0) + bkq);                                    \
    } while (0)

    #define STORE_CHUNK(buf) do {                                                   \
        if (MODE == 1) {                                                            \
            *(uint4*)&As[buf][kk*ASTR1 + pg*8]     = tf4(pa0);                      \
            *(uint4*)&As[buf][kk*ASTR1 + pg*8 + 4] = tf4(pa1);                      \
        } else {                                                                    \
            *(uint4*)&As[buf][am*ASTR + akq]     = tf4(pa0);                        \
            *(uint4*)&As[buf][am*ASTR + akq + 4] = tf4(pa1);                        \
        }                                                                           \
        *(uint4*)&Bs[buf][bn_*BSTR + bkq] = tf4(pb);                                \
    } while (0)

    LOAD_CHUNK(0);
    STORE_CHUNK(0);
    __syncthreads();

    #pragma unroll 1
    for (int cch = 0; cch < 16; cch++) {
        const int buf = cch & 1;
        if (cch < 15) LOAD_CHUNK((cch + 1) * 16);
        const unsigned* Ab = As[buf];
        const unsigned aoff = as_base + (unsigned)buf * 2560u * 4u;
        const unsigned boff = bs_base + (unsigned)buf * 1280u * 4u;
        #pragma unroll
        for (int ks = 0; ks < 2; ks++) {
            const int k8 = ks * 8;
            unsigned a[2][4], b[2][4];
            if (MODE == 1) {
                #pragma unroll
                for (int mi = 0; mi < 2; mi++) {
                    int mr = mw + mi*16 + g;
                    a[mi][0] = Ab[(k8 + t)*ASTR1 + mr];
                    a[mi][1] = Ab[(k8 + t)*ASTR1 + mr + 8];
                    a[mi][2] = Ab[(k8 + t + 4)*ASTR1 + mr];
                    a[mi][3] = Ab[(k8 + t + 4)*ASTR1 + mr + 8];
                }
            } else {
                #pragma unroll
                for (int mi = 0; mi < 2; mi++)
                    ldmx4(a[mi], aoff + ((unsigned)((arow + mi*16)*ASTR + k8 + acol) << 2));
            }
            #pragma unroll
            for (int np = 0; np < 2; np++)
                ldmx4(b[np], boff + ((unsigned)((brow + np*16)*BSTR + k8 + bcol) << 2));
            #pragma unroll
            for (int mi = 0; mi < 2; mi++) {
                mma1688(c_[mi][0], a[mi], &b[0][0]);
                mma1688(c_[mi][1], a[mi], &b[0][2]);
                mma1688(c_[mi][2], a[mi], &b[1][0]);
                mma1688(c_[mi][3], a[mi], &b[1][2]);
            }
        }
        if (cch < 15) STORE_CHUNK(buf ^ 1);
        __syncthreads();
    }

    // ---- epilogue ----
    #pragma unroll
    for (int mi = 0; mi < 2; mi++) {
        #pragma unroll
        for (int ni = 0; ni < 4; ni++) {
            const int jc = j0 + nw + ni*8 + 2*t;
            const int r0 = mw + mi*16 + g;
            const float* cr = c_[mi][ni];
            if (MODE == 1) {
                const int h = jc >> 5, hd = jc & 31;
                float b0 = d_bias2[camI*DIM + jc], b1 = d_bias2[camI*DIM + jc + 1];
                __half* o0 = d_value + ((size_t)(camI*NH + h)*HWF + p0 + r0)*HD + hd;
                __half* o1 = o0 + 8*HD;
                *(__half2*)o0 = __floats2half2_rn(cr[0] + b0, cr[1] + b1);
                *(__half2*)o1 = __floats2half2_rn(cr[2] + b0, cr[3] + b1);
            } else if (MODE == 2) {
                float b0, b1;
                if (jc < 128) { b0 = bias0[jc]; b1 = bias0[jc+1]; }
                else          { b0 = bias1[jc-128]; b1 = bias1[jc-127]; }
                int mr0 = m0 + r0, mr1 = mr0 + 8;
                if (mr0 < MROWS)
                    *(float2*)&d_offattn[(size_t)mr0*OAC + jc] = make_float2(cr[0]+b0, cr[1]+b1);
                if (mr1 < MROWS)
                    *(float2*)&d_offattn[(size_t)mr1*OAC + jc] = make_float2(cr[2]+b0, cr[3]+b1);
            } else {
                float b0 = bias0[jc] , b1 = bias0[jc+1];
                float e0 = d_bi2[jc], e1 = d_bi2[jc+1];
                int mr0 = m0 + r0, mr1 = mr0 + 8;
                if (mr0 < QN) {
                    float gf = d_gflag[mr0];
                    *(float2*)&C[(size_t)mr0*DIM + jc] =
                        make_float2(cr[0] + b0 + gf*e0, cr[1] + b1 + gf*e1);
                }
                if (mr1 < QN) {
                    float gf = d_gflag[mr1];
                    *(float2*)&C[(size_t)mr1*DIM + jc] =
                        make_float2(cr[2] + b0 + gf*e0, cr[3] + b1 + gf*e1);
                }
            }
        }
    }
    #undef LOAD_CHUNK
    #undef STORE_CHUNK
}

// ---------------- sampling + softmax + camera reduction (fp16 value table) ----------------
__global__ __launch_bounds__(256) void sample_kernel(const float* __restrict__ ref,
                                                     const void* __restrict__ mask) {
    const int q = blockIdx.x;
    const int tid = threadIdx.x;
    const int h = tid>>5, l = tid&31;
    const int corner = l>>3, c8 = l&7;
    const int ox = corner&1, oy = corner>>1;
    __shared__ float s_hit[NCAM];
    __shared__ float s_inv, s_g;
    if (tid < NCAM) {
        const int mode = d_mask_mode;
        size_t base = (size_t)(tid*QN + q)*8;
        int hit = mask_elem(mask, base+0, mode) | mask_elem(mask, base+2, mode) |
                  mask_elem(mask, base+4, mode) | mask_elem(mask, base+6, mode);
        s_hit[tid] = hit ? 1.f : 0.f;
    }
    __syncthreads();
    if (tid == 0) {
        float c = s_hit[0]+s_hit[1]+s_hit[2]+s_hit[3]+s_hit[4]+s_hit[5];
        s_g = (c > 0.f) ? 1.f : 0.f;
        s_inv = 1.f / fmaxf(c, 1.f);
    }
    __syncthreads();
    float ax=0.f, ay=0.f, az=0.f, aw=0.f;
    for (int camI = 0; camI < NCAM; camI++) {
        if (s_hit[camI] == 0.f) continue;
        const float* row = d_offattn + (size_t)(camI*QN + q)*OAC;
        float logit = row[128 + h*8 + c8];
        float ofx   = row[h*16 + c8*2];
        float ofy   = row[h*16 + c8*2 + 1];
        const float* rp = ref + ((size_t)(camI*QN + q)*4 + (c8&3))*2;
        float rx = rp[0], ry = rp[1];
        float mx = logit;
        mx = fmaxf(mx, __shfl_xor_sync(0xffffffffu, mx, 1, 8));
        mx = fmaxf(mx, __shfl_xor_sync(0xffffffffu, mx, 2, 8));
        mx = fmaxf(mx, __shfl_xor_sync(0xffffffffu, mx, 4, 8));
        float e = __expf(logit - mx);
        float sm = e;
        sm += __shfl_xor_sync(0xffffffffu, sm, 1, 8);
        sm += __shfl_xor_sync(0xffffffffu, sm, 2, 8);
        sm += __shfl_xor_sync(0xffffffffu, sm, 4, 8);
        float w = e / sm;
        const __half* vb = d_value + (size_t)(camI*NH + h)*HWF*HD + c8*4;
        #pragma unroll
        for (int p = 0; p < 8; p++) {
            float wp  = __shfl_sync(0xffffffffu, w,   p, 8);
            float fx  = __shfl_sync(0xffffffffu, ofx, p, 8);
            float fy  = __shfl_sync(0xffffffffu, ofy, p, 8);
            float rxp = __shfl_sync(0xffffffffu, rx,  p, 8);
            float ryp = __shfl_sync(0xffffffffu, ry,  p, 8);
            float x = fmaf(rxp, (float)WFv, fx) - 0.5f;
            float y = fmaf(ryp, (float)HFv, fy) - 0.5f;
            float xf = floorf(x), yf = floorf(y);
            float dx = x - xf, dy = y - yf;
            int xi = (int)xf + ox;
            int yi = (int)yf + oy;
            float wx = ox ? dx : (1.f - dx);
            float wy = oy ? dy : (1.f - dy);
            bool valid = (xi >= 0) && (xi < WFv) && (yi >= 0) && (yi < HFv);
            float wc = valid ? (wp*wx*wy) : 0.f;
            int pix = min(max(yi,0),HFv-1)*WFv + min(max(xi,0),WFv-1);
            uint2 raw = *(const uint2*)(vb + (size_t)pix*HD);
            float2 f0 = __half22float2(*(__half2*)&raw.x);
            float2 f1 = __half22float2(*(__half2*)&raw.y);
            ax = fmaf(wc, f0.x, ax); ay = fmaf(wc, f0.y, ay);
            az = fmaf(wc, f1.x, az); aw = fmaf(wc, f1.y, aw);
        }
    }
    ax += __shfl_xor_sync(0xffffffffu, ax, 8);  ax += __shfl_xor_sync(0xffffffffu, ax, 16);
    ay += __shfl_xor_sync(0xffffffffu, ay, 8);  ay += __shfl_xor_sync(0xffffffffu, ay, 16);
    az += __shfl_xor_sync(0xffffffffu, az, 8);  az += __shfl_xor_sync(0xffffffffu, az, 16);
    aw += __shfl_xor_sync(0xffffffffu, aw, 8);  aw += __shfl_xor_sync(0xffffffffu, aw, 16);
    if (l < 8) {
        float inv = s_inv;
        float4 o = make_float4(ax*inv, ay*inv, az*inv, aw*inv);
        *(float4*)&d_S[(size_t)q*DIM + h*HD + c8*4] = o;
    }
    if (tid == 0) d_gflag[q] = s_g;
}

// ---------------- launch ----------------
extern "C" void kernel_launch(void* const* d_in, const int* in_sizes, int n_in,
                              void* d_out, int out_size) {
    const float* queries = (const float*)d_in[0];
    const float* pos     = (const float*)d_in[1];
    const float* lvl     = (const float*)d_in[2];
    const float* camemb  = (const float*)d_in[3];
    const float* feat    = (const float*)d_in[4];
    const float* ref     = (const float*)d_in[5];
    const void*  mask    = (const void*)d_in[6];
    const float* W_value = (const float*)d_in[7];
    const float* b_value = (const float*)d_in[8];
    const float* W_off   = (const float*)d_in[9];
    const float* b_off   = (const float*)d_in[10];
    const float* W_attn  = (const float*)d_in[11];
    const float* b_attn  = (const float*)d_in[12];
    const float* W_inner = (const float*)d_in[13];
    const float* b_inner = (const float*)d_in[14];
    const float* W_out   = (const float*)d_in[15];
    const float* b_out   = (const float*)d_in[16];
    float* out = (float*)d_out;

    prep_a<<<NCAM + 1, DIM>>>(lvl, camemb, W_value, b_value, (const unsigned int*)mask);
    gemm_tc<1><<<dim3(4, 132), 256>>>(feat, nullptr, W_value, nullptr,
                                      nullptr, nullptr, nullptr);
    gemm_tc<2><<<dim3(3, 469), 256>>>(queries, pos, W_off, W_attn,
                                      b_off, b_attn, nullptr);
    sample_kernel<<<QN, 256>>>(ref, mask);
    prep_b<<<DIM + 1, DIM>>>(W_out, W_inner, b_inner);
    gemm_tc<3><<<dim3(4, 79), 256>>>(nullptr, nullptr, nullptr, nullptr,
                                     b_out, nullptr, out);
    (void)in_sizes; (void)n_in; (void)out_size;
}

// round 8
// speedup vs baseline: 1.2332x; 1.2332x over previous
#include <cuda_runtime.h>
#include <cuda_fp16.h>
#include <cstdint>

#define QN   10000
#define NCAM 6
#define DIM  256
#define HWF  2816     // 32*88
#define NH   8
#define HD   32
#define HFv  32
#define WFv  88
#define MROWS (NCAM*QN)   // 60000
#define OAC  192          // 128 offsets + 64 attn logits

// ---------------- scratch ----------------
__device__ __half d_value[NCAM*NH*HWF*HD];  // (cam, head, hw, hd) fp16
__device__ float d_offattn[(size_t)MROWS*OAC];
__device__ float d_S[(size_t)QN*DIM];
__device__ float d_gflag[QN];
__device__ float d_bias2[NCAM*DIM];
__device__ float d_Wc[DIM*DIM];             // W_out @ W_inner
__device__ float d_bi2[DIM];                // W_out @ b_inner
__device__ int   d_mask_mode;               // 0=u8, 1=i32, 2=f32

__device__ __forceinline__ int mask_elem(const void* mask, size_t idx, int mode) {
    if (mode == 0) return ((const unsigned char*)mask)[idx] != 0;
    if (mode == 1) return ((const int*)mask)[idx] != 0;
    return ((const float*)mask)[idx] != 0.f;
}

// ---------------- prep A: bias2 (blocks 0..5) + mask detect (block 6) ----------------
__global__ void prep_a(const float* __restrict__ lvl, const float* __restrict__ camemb,
                       const float* __restrict__ Wv, const float* __restrict__ bv,
                       const unsigned int* __restrict__ mk) {
    int c = blockIdx.x, j = threadIdx.x;
    if (c == NCAM) {
        if (j < 32) {
            bool f = false, multi = false;
            for (int i = j; i < 256; i += 32) {
                unsigned int w = mk[i];
                f |= (w == 0x3F800000u);
                multi |= (w != 0x3F800000u && w > 1u);
            }
            unsigned bf = __ballot_sync(0xffffffffu, f), bm = __ballot_sync(0xffffffffu, multi);
            if (j == 0) d_mask_mode = bf ? 2 : (bm ? 0 : 1);
        }
        return;
    }
    __shared__ float e[DIM];
    e[j] = lvl[j] + camemb[c*DIM + j];
    __syncthreads();
    const float4* w4 = (const float4*)(Wv + (size_t)j*DIM);
    const float4* e4 = (const float4*)e;
    float s = bv[j];
    #pragma unroll 8
    for (int k = 0; k < DIM/4; k++) {
        float4 w = w4[k]; float4 ev = e4[k];
        s += w.x*ev.x + w.y*ev.y + w.z*ev.z + w.w*ev.w;
    }
    d_bias2[c*DIM + j] = s;
}

// ---------------- prep B: Wc (blocks 0..255) + bi2 (block 256) ----------------
__global__ void prep_b(const float* __restrict__ Wo, const float* __restrict__ Wi,
                       const float* __restrict__ bi) {
    int i = blockIdx.x, j = threadIdx.x;
    if (i == DIM) {
        int w = j >> 5, l = j & 31;
        for (int ii = w; ii < DIM; ii += 8) {
            float s = 0.f;
            #pragma unroll
            for (int t = 0; t < 8; t++) {
                int k = l + 32*t;
                s += Wo[(size_t)ii*DIM + k] * bi[k];
            }
            #pragma unroll
            for (int o = 16; o; o >>= 1) s += __shfl_xor_sync(0xffffffffu, s, o);
            if (l == 0) d_bi2[ii] = s;
        }
        return;
    }
    __shared__ float wo[DIM];
    wo[j] = Wo[(size_t)i*DIM + j];
    __syncthreads();
    float s = 0.f;
    #pragma unroll 8
    for (int k = 0; k < DIM; k++) s += wo[k] * Wi[(size_t)k*DIM + j];
    d_Wc[(size_t)i*DIM + j] = s;
}

// ---------------- tf32 mma.sync GEMM core (ldmatrix operand fetch) ----------------
#define ASTR 20
#define ASTR1 136
#define BSTR 20

__device__ __forceinline__ unsigned f2tf(float f) {
    unsigned u; asm("cvt.rna.tf32.f32 %0, %1;" : "=r"(u) : "f"(f)); return u;
}
__device__ __forceinline__ void mma1688(float* c, const unsigned* a, const unsigned* b) {
    asm volatile("mma.sync.aligned.m16n8k8.row.col.f32.tf32.tf32.f32 "
        "{%0,%1,%2,%3}, {%4,%5,%6,%7}, {%8,%9}, {%0,%1,%2,%3};"
        : "+f"(c[0]), "+f"(c[1]), "+f"(c[2]), "+f"(c[3])
        : "r"(a[0]), "r"(a[1]), "r"(a[2]), "r"(a[3]), "r"(b[0]), "r"(b[1]));
}
__device__ __forceinline__ uint4 tf4(float4 v) {
    return make_uint4(f2tf(v.x), f2tf(v.y), f2tf(v.z), f2tf(v.w));
}
__device__ __forceinline__ void ldmx4(unsigned* r, unsigned addr) {
    asm volatile("ldmatrix.sync.aligned.m8n8.x4.shared.b16 {%0,%1,%2,%3}, [%4];"
        : "=r"(r[0]), "=r"(r[1]), "=r"(r[2]), "=r"(r[3]) : "r"(addr));
}
__device__ __forceinline__ unsigned smem_addr(const void* p) {
    return (unsigned)__cvta_generic_to_shared(p);
}

template<int MODE>
__global__ __launch_bounds__(256, 2) void gemm_tc(
    const float* __restrict__ A0, const float* __restrict__ A1,
    const float* __restrict__ B0, const float* __restrict__ B1,
    const float* __restrict__ bias0, const float* __restrict__ bias1,
    float* __restrict__ C)
{
    __shared__ unsigned As[2][2560];
    __shared__ unsigned Bs[2][1280];
    const int tid = threadIdx.x;
    const int lane = tid & 31, wid = tid >> 5;
    const int mw = (wid & 3) * 32, nw = (wid >> 2) * 32;
    const int g = lane >> 2, t = lane & 3;
    const int j0 = blockIdx.x * 64;

    int camI = 0, p0 = 0, m0 = 0;
    if (MODE == 1) { camI = blockIdx.y / 22; p0 = (blockIdx.y % 22) * 128; }
    else m0 = blockIdx.y * 128;
    const int Mrows = (MODE == 2) ? MROWS : QN;

    const float* Aptr = (MODE == 3) ? (const float*)d_S : A0;
    const int bn_ = tid >> 2, bkq = (tid & 3) * 4;
    const int jg = j0 + bn_;
    const float* wrow;
    if (MODE == 2) wrow = (jg < 128) ? (B0 + (size_t)jg*DIM) : (B1 + (size_t)(jg-128)*DIM);
    else if (MODE == 3) wrow = (const float*)d_Wc + (size_t)jg*DIM;
    else wrow = B0 + (size_t)jg*DIM;

    const int am = tid >> 1, akq = (tid & 1) * 8;       // MODE 2/3 A staging
    const int kk = tid >> 4, pg = tid & 15;             // MODE 1 A staging
    const int mga = m0 + am;

    const unsigned as_base = smem_addr(&As[0][0]);
    const unsigned bs_base = smem_addr(&Bs[0][0]);
    const int arow = mw + (lane & 7) + ((lane >> 3) & 1) * 8;
    const int acol = ((lane >> 4) & 1) * 4;
    const int brow = nw + (lane & 7) + ((lane >> 4) & 1) * 8;
    const int bcol = ((lane >> 3) & 1) * 4;

    float c_[2][4][4];
    #pragma unroll
    for (int mi = 0; mi < 2; mi++)
        #pragma unroll
        for (int ni = 0; ni < 4; ni++)
            #pragma unroll
            for (int r = 0; r < 4; r++) c_[mi][ni][r] = 0.f;

    float4 pa0, pa1, pb;
    auto zero4 = make_float4(0.f, 0.f, 0.f, 0.f);
    #define LOAD_CHUNK(k0) do {                                                      \
        if (MODE == 1) {                                                             \
            const float* src = A0 + ((size_t)(camI*DIM + (k0) + kk))*HWF + p0 + pg*8;\
            pa0 = *(const float4*)src; pa1 = *(const float4*)(src + 4);              \
        } else {                                                                     \
            pa0 = zero4; pa1 = zero4;                                                \
            if (mga < Mrows) {                                                       \
                pa0 = *(const float4*)(Aptr + (size_t)mga*DIM + (k0) + akq);         \
                pa1 = *(const float4*)(Aptr + (size_t)mga*DIM + (k0) + akq + 4);     \
                if (MODE == 2) {                                                     \
                    float4 q0 = *(const float4*)(A1 + (size_t)mga*DIM + (k0) + akq); \
                    float4 q1 = *(const float4*)(A1 + (size_t)mga*DIM + (k0) + akq+4);\
                    pa0.x+=q0.x; pa0.y+=q0.y; pa0.z+=q0.z; pa0.w+=q0.w;              \
                    pa1.x+=q1.x; pa1.y+=q1.y; pa1.z+=q1.z; pa1.w+=q1.w;              \
                }                                                                    \
            }                                                                        \
        }                                                                            \
        pb = *(const float4*)(wrow + (k0) + bkq);                                    \
    } while (0)

    #define STORE_CHUNK(buf) do {                                                   \
        if (MODE == 1) {                                                            \
            *(uint4*)&As[buf][kk*ASTR1 + pg*8]     = tf4(pa0);                      \
            *(uint4*)&As[buf][kk*ASTR1 + pg*8 + 4] = tf4(pa1);                      \
        } else {                                                                    \
            *(uint4*)&As[buf][am*ASTR + akq]     = tf4(pa0);                        \
            *(uint4*)&As[buf][am*ASTR + akq + 4] = tf4(pa1);                        \
        }                                                                           \
        *(uint4*)&Bs[buf][bn_*BSTR + bkq] = tf4(pb);                                \
    } while (0)

    LOAD_CHUNK(0);
    STORE_CHUNK(0);
    __syncthreads();

    #pragma unroll 1
    for (int cch = 0; cch < 16; cch++) {
        const int buf = cch & 1;
        if (cch < 15) LOAD_CHUNK((cch + 1) * 16);
        const unsigned* Ab = As[buf];
        const unsigned aoff = as_base + (unsigned)buf * 2560u * 4u;
        const unsigned boff = bs_base + (unsigned)buf * 1280u * 4u;
        #pragma unroll
        for (int ks = 0; ks < 2; ks++) {
            const int k8 = ks * 8;
            unsigned a[2][4], b[2][4];
            if (MODE == 1) {
                #pragma unroll
                for (int mi = 0; mi < 2; mi++) {
                    int mr = mw + mi*16 + g;
                    a[mi][0] = Ab[(k8 + t)*ASTR1 + mr];
                    a[mi][1] = Ab[(k8 + t)*ASTR1 + mr + 8];
                    a[mi][2] = Ab[(k8 + t + 4)*ASTR1 + mr];
                    a[mi][3] = Ab[(k8 + t + 4)*ASTR1 + mr + 8];
                }
            } else {
                #pragma unroll
                for (int mi = 0; mi < 2; mi++)
                    ldmx4(a[mi], aoff + ((unsigned)((arow + mi*16)*ASTR + k8 + acol) << 2));
            }
            #pragma unroll
            for (int np = 0; np < 2; np++)
                ldmx4(b[np], boff + ((unsigned)((brow + np*16)*BSTR + k8 + bcol) << 2));
            #pragma unroll
            for (int mi = 0; mi < 2; mi++) {
                mma1688(c_[mi][0], a[mi], &b[0][0]);
                mma1688(c_[mi][1], a[mi], &b[0][2]);
                mma1688(c_[mi][2], a[mi], &b[1][0]);
                mma1688(c_[mi][3], a[mi], &b[1][2]);
            }
        }
        if (cch < 15) STORE_CHUNK(buf ^ 1);
        __syncthreads();
    }

    // ---- epilogue ----
    #pragma unroll
    for (int mi = 0; mi < 2; mi++) {
        #pragma unroll
        for (int ni = 0; ni < 4; ni++) {
            const int jc = j0 + nw + ni*8 + 2*t;
            const int r0 = mw + mi*16 + g;
            const float* cr = c_[mi][ni];
            if (MODE == 1) {
                const int h = jc >> 5, hd = jc & 31;
                float b0 = d_bias2[camI*DIM + jc], b1 = d_bias2[camI*DIM + jc + 1];
                __half* o0 = d_value + ((size_t)(camI*NH + h)*HWF + p0 + r0)*HD + hd;
                __half* o1 = o0 + 8*HD;
                *(__half2*)o0 = __floats2half2_rn(cr[0] + b0, cr[1] + b1);
                *(__half2*)o1 = __floats2half2_rn(cr[2] + b0, cr[3] + b1);
            } else if (MODE == 2) {
                float b0, b1;
                if (jc < 128) { b0 = bias0[jc]; b1 = bias0[jc+1]; }
                else          { b0 = bias1[jc-128]; b1 = bias1[jc-127]; }
                int mr0 = m0 + r0, mr1 = mr0 + 8;
                if (mr0 < MROWS)
                    *(float2*)&d_offattn[(size_t)mr0*OAC + jc] = make_float2(cr[0]+b0, cr[1]+b1);
                if (mr1 < MROWS)
                    *(float2*)&d_offattn[(size_t)mr1*OAC + jc] = make_float2(cr[2]+b0, cr[3]+b1);
            } else {
                float b0 = bias0[jc] , b1 = bias0[jc+1];
                float e0 = d_bi2[jc], e1 = d_bi2[jc+1];
                int mr0 = m0 + r0, mr1 = mr0 + 8;
                if (mr0 < QN) {
                    float gf = d_gflag[mr0];
                    *(float2*)&C[(size_t)mr0*DIM + jc] =
                        make_float2(cr[0] + b0 + gf*e0, cr[1] + b1 + gf*e1);
                }
                if (mr1 < QN) {
                    float gf = d_gflag[mr1];
                    *(float2*)&C[(size_t)mr1*DIM + jc] =
                        make_float2(cr[2] + b0 + gf*e0, cr[3] + b1 + gf*e1);
                }
            }
        }
    }
    #undef LOAD_CHUNK
    #undef STORE_CHUNK
}

// ---------------- sampling: compute-once, shuffle-results ----------------
// lane = corner(2b) x point/channel-quad(3b); each lane computes its OWN point's
// (pix, wc) for its OWN corner once per camera; p-loop shuffles just 2 values.
__global__ __launch_bounds__(256) void sample_kernel(const float* __restrict__ ref,
                                                     const void* __restrict__ mask) {
    const int q = blockIdx.x;
    const int tid = threadIdx.x;
    const int h = tid>>5, l = tid&31;
    const int c8 = l&7;
    const int ox = (l>>3)&1, oy = l>>4;
    __shared__ float s_hit[NCAM];
    __shared__ float s_inv, s_g;
    if (tid < NCAM) {
        const int mode = d_mask_mode;
        size_t base = (size_t)(tid*QN + q)*8;
        int hit = mask_elem(mask, base+0, mode) | mask_elem(mask, base+2, mode) |
                  mask_elem(mask, base+4, mode) | mask_elem(mask, base+6, mode);
        s_hit[tid] = hit ? 1.f : 0.f;
    }
    __syncthreads();
    if (tid == 0) {
        float c = s_hit[0]+s_hit[1]+s_hit[2]+s_hit[3]+s_hit[4]+s_hit[5];
        s_g = (c > 0.f) ? 1.f : 0.f;
        s_inv = 1.f / fmaxf(c, 1.f);
    }
    __syncthreads();
    float ax=0.f, ay=0.f, az=0.f, aw=0.f;
    for (int camI = 0; camI < NCAM; camI++) {
        if (s_hit[camI] == 0.f) continue;
        const float* row = d_offattn + (size_t)(camI*QN + q)*OAC;
        float logit = row[128 + h*8 + c8];
        float ofx   = row[h*16 + c8*2];
        float ofy   = row[h*16 + c8*2 + 1];
        const float* rp = ref + ((size_t)(camI*QN + q)*4 + (c8&3))*2;
        float rx = rp[0], ry = rp[1];
        // softmax over 8 points (intra-8-lane group)
        float mx = logit;
        mx = fmaxf(mx, __shfl_xor_sync(0xffffffffu, mx, 1, 8));
        mx = fmaxf(mx, __shfl_xor_sync(0xffffffffu, mx, 2, 8));
        mx = fmaxf(mx, __shfl_xor_sync(0xffffffffu, mx, 4, 8));
        float e = __expf(logit - mx);
        float sm = e;
        sm += __shfl_xor_sync(0xffffffffu, sm, 1, 8);
        sm += __shfl_xor_sync(0xffffffffu, sm, 2, 8);
        sm += __shfl_xor_sync(0xffffffffu, sm, 4, 8);
        float w = e / sm;
        // position + weight for OWN point (c8) at OWN corner (ox,oy) — once
        float x = fmaf(rx, (float)WFv, ofx) - 0.5f;
        float y = fmaf(ry, (float)HFv, ofy) - 0.5f;
        float xf = floorf(x), yf = floorf(y);
        float dx = x - xf, dy = y - yf;
        int xi = (int)xf + ox;
        int yi = (int)yf + oy;
        float wx = ox ? dx : (1.f - dx);
        float wy = oy ? dy : (1.f - dy);
        bool valid = (xi >= 0) && (xi < WFv) && (yi >= 0) && (yi < HFv);
        float wc = valid ? (w*wx*wy) : 0.f;
        int pix = min(max(yi,0),HFv-1)*WFv + min(max(xi,0),WFv-1);
        const __half* vb = d_value + (size_t)(camI*NH + h)*HWF*HD + c8*4;
        #pragma unroll
        for (int p = 0; p < 8; p++) {
            float wcp = __shfl_sync(0xffffffffu, wc,  p, 8);
            int  pixp = __shfl_sync(0xffffffffu, pix, p, 8);
            uint2 raw = *(const uint2*)(vb + (size_t)pixp*HD);
            float2 f0 = __half22float2(*(__half2*)&raw.x);
            float2 f1 = __half22float2(*(__half2*)&raw.y);
            ax = fmaf(wcp, f0.x, ax); ay = fmaf(wcp, f0.y, ay);
            az = fmaf(wcp, f1.x, az); aw = fmaf(wcp, f1.y, aw);
        }
    }
    // reduce the 4 corner groups (lanes differ in bits 3,4)
    ax += __shfl_xor_sync(0xffffffffu, ax, 8);  ax += __shfl_xor_sync(0xffffffffu, ax, 16);
    ay += __shfl_xor_sync(0xffffffffu, ay, 8);  ay += __shfl_xor_sync(0xffffffffu, ay, 16);
    az += __shfl_xor_sync(0xffffffffu, az, 8);  az += __shfl_xor_sync(0xffffffffu, az, 16);
    aw += __shfl_xor_sync(0xffffffffu, aw, 8);  aw += __shfl_xor_sync(0xffffffffu, aw, 16);
    if (l < 8) {
        float inv = s_inv;
        float4 o = make_float4(ax*inv, ay*inv, az*inv, aw*inv);
        *(float4*)&d_S[(size_t)q*DIM + h*HD + c8*4] = o;
    }
    if (tid == 0) d_gflag[q] = s_g;
}

// ---------------- launch ----------------
extern "C" void kernel_launch(void* const* d_in, const int* in_sizes, int n_in,
                              void* d_out, int out_size) {
    const float* queries = (const float*)d_in[0];
    const float* pos     = (const float*)d_in[1];
    const float* lvl     = (const float*)d_in[2];
    const float* camemb  = (const float*)d_in[3];
    const float* feat    = (const float*)d_in[4];
    const float* ref     = (const float*)d_in[5];
    const void*  mask    = (const void*)d_in[6];
    const float* W_value = (const float*)d_in[7];
    const float* b_value = (const float*)d_in[8];
    const float* W_off   = (const float*)d_in[9];
    const float* b_off   = (const float*)d_in[10];
    const float* W_attn  = (const float*)d_in[11];
    const float* b_attn  = (const float*)d_in[12];
    const float* W_inner = (const float*)d_in[13];
    const float* b_inner = (const float*)d_in[14];
    const float* W_out   = (const float*)d_in[15];
    const float* b_out   = (const float*)d_in[16];
    float* out = (float*)d_out;

    prep_a<<<NCAM + 1, DIM>>>(lvl, camemb, W_value, b_value, (const unsigned int*)mask);
    gemm_tc<1><<<dim3(4, 132), 256>>>(feat, nullptr, W_value, nullptr,
                                      nullptr, nullptr, nullptr);
    gemm_tc<2><<<dim3(3, 469), 256>>>(queries, pos, W_off, W_attn,
                                      b_off, b_attn, nullptr);
    sample_kernel<<<QN, 256>>>(ref, mask);
    prep_b<<<DIM + 1, DIM>>>(W_out, W_inner, b_inner);
    gemm_tc<3><<<dim3(4, 79), 256>>>(nullptr, nullptr, nullptr, nullptr,
                                     b_out, nullptr, out);
    (void)in_sizes; (void)n_in; (void)out_size;
}

// round 9
// speedup vs baseline: 1.3101x; 1.0624x over previous
#include <cuda_runtime.h>
#include <cuda_fp16.h>
#include <cstdint>

#define QN   10000
#define NCAM 6
#define DIM  256
#define HWF  2816     // 32*88
#define NH   8
#define HD   32
#define HFv  32
#define WFv  88
#define MROWS (NCAM*QN)   // 60000
#define OAC  192          // 128 offsets + 64 attn logits

// ---------------- scratch ----------------
__device__ __half d_value[NCAM*NH*HWF*HD];  // (cam, head, hw, hd) fp16
__device__ float d_offattn[(size_t)MROWS*OAC];
__device__ float d_S[(size_t)QN*DIM];
__device__ float d_gflag[QN];
__device__ float d_bias2[NCAM*DIM];
__device__ float d_Wc[DIM*DIM];             // W_out @ W_inner
__device__ float d_bi2[DIM];                // W_out @ b_inner
__device__ int   d_mask_mode;               // 0=u8, 1=i32, 2=f32

__device__ __forceinline__ int mask_elem(const void* mask, size_t idx, int mode) {
    if (mode == 0) return ((const unsigned char*)mask)[idx] != 0;
    if (mode == 1) return ((const int*)mask)[idx] != 0;
    return ((const float*)mask)[idx] != 0.f;
}

// ---------------- prep A: bias2 (blocks 0..5) + mask detect (block 6) ----------------
__global__ void prep_a(const float* __restrict__ lvl, const float* __restrict__ camemb,
                       const float* __restrict__ Wv, const float* __restrict__ bv,
                       const unsigned int* __restrict__ mk) {
    int c = blockIdx.x, j = threadIdx.x;
    if (c == NCAM) {
        if (j < 32) {
            bool f = false, multi = false;
            for (int i = j; i < 256; i += 32) {
                unsigned int w = mk[i];
                f |= (w == 0x3F800000u);
                multi |= (w != 0x3F800000u && w > 1u);
            }
            unsigned bf = __ballot_sync(0xffffffffu, f), bm = __ballot_sync(0xffffffffu, multi);
            if (j == 0) d_mask_mode = bf ? 2 : (bm ? 0 : 1);
        }
        return;
    }
    __shared__ float e[DIM];
    e[j] = lvl[j] + camemb[c*DIM + j];
    __syncthreads();
    const float4* w4 = (const float4*)(Wv + (size_t)j*DIM);
    const float4* e4 = (const float4*)e;
    float s = bv[j];
    #pragma unroll 8
    for (int k = 0; k < DIM/4; k++) {
        float4 w = w4[k]; float4 ev = e4[k];
        s += w.x*ev.x + w.y*ev.y + w.z*ev.z + w.w*ev.w;
    }
    d_bias2[c*DIM + j] = s;
}

// ---------------- prep B: Wc (blocks 0..255) + bi2 (block 256) ----------------
__global__ void prep_b(const float* __restrict__ Wo, const float* __restrict__ Wi,
                       const float* __restrict__ bi) {
    int i = blockIdx.x, j = threadIdx.x;
    if (i == DIM) {
        int w = j >> 5, l = j & 31;
        for (int ii = w; ii < DIM; ii += 8) {
            float s = 0.f;
            #pragma unroll
            for (int t = 0; t < 8; t++) {
                int k = l + 32*t;
                s += Wo[(size_t)ii*DIM + k] * bi[k];
            }
            #pragma unroll
            for (int o = 16; o; o >>= 1) s += __shfl_xor_sync(0xffffffffu, s, o);
            if (l == 0) d_bi2[ii] = s;
        }
        return;
    }
    __shared__ float wo[DIM];
    wo[j] = Wo[(size_t)i*DIM + j];
    __syncthreads();
    float s = 0.f;
    #pragma unroll 8
    for (int k = 0; k < DIM; k++) s += wo[k] * Wi[(size_t)k*DIM + j];
    d_Wc[(size_t)i*DIM + j] = s;
}

// ---------------- fp16 mma.sync m16n8k16 GEMM core ----------------
// A smem: MODE 2/3 [m=128][24 fp16] (16 data + 8 pad, 48B rows)
//         MODE 1   [k=16][136 fp16] (128 data + 8 pad, 272B rows, ldmatrix.trans)
// B smem: [n=64][24 fp16]
#define AST 24
#define MSTR 136
#define BST 24

__device__ __forceinline__ unsigned p2(float x, float y) {
    __half2 h = __floats2half2_rn(x, y);
    return *(unsigned*)&h;
}
__device__ __forceinline__ void mma16816(float* c, const unsigned* a, unsigned b0, unsigned b1) {
    asm volatile("mma.sync.aligned.m16n8k16.row.col.f32.f16.f16.f32 "
        "{%0,%1,%2,%3}, {%4,%5,%6,%7}, {%8,%9}, {%0,%1,%2,%3};"
        : "+f"(c[0]), "+f"(c[1]), "+f"(c[2]), "+f"(c[3])
        : "r"(a[0]), "r"(a[1]), "r"(a[2]), "r"(a[3]), "r"(b0), "r"(b1));
}
__device__ __forceinline__ void ldmx4(unsigned* r, unsigned addr) {
    asm volatile("ldmatrix.sync.aligned.m8n8.x4.shared.b16 {%0,%1,%2,%3}, [%4];"
        : "=r"(r[0]), "=r"(r[1]), "=r"(r[2]), "=r"(r[3]) : "r"(addr));
}
__device__ __forceinline__ void ldmx4t(unsigned* r, unsigned addr) {
    asm volatile("ldmatrix.sync.aligned.m8n8.x4.trans.shared.b16 {%0,%1,%2,%3}, [%4];"
        : "=r"(r[0]), "=r"(r[1]), "=r"(r[2]), "=r"(r[3]) : "r"(addr));
}
__device__ __forceinline__ unsigned smem_addr(const void* p) {
    return (unsigned)__cvta_generic_to_shared(p);
}

template<int MODE>
__global__ __launch_bounds__(256, 2) void gemm_tc(
    const float* __restrict__ A0, const float* __restrict__ A1,
    const float* __restrict__ B0, const float* __restrict__ B1,
    const float* __restrict__ bias0, const float* __restrict__ bias1,
    float* __restrict__ C)
{
    __shared__ __half As[2][3072];   // MODE1 uses 16*136=2176 of it
    __shared__ __half Bs[2][1536];
    const int tid = threadIdx.x;
    const int lane = tid & 31, wid = tid >> 5;
    const int mw = (wid & 3) * 32, nw = (wid >> 2) * 32;
    const int g = lane >> 2, t = lane & 3;
    const int j0 = blockIdx.x * 64;

    int camI = 0, p0 = 0, m0 = 0;
    if (MODE == 1) { camI = blockIdx.y / 22; p0 = (blockIdx.y % 22) * 128; }
    else m0 = blockIdx.y * 128;
    const int Mrows = (MODE == 2) ? MROWS : QN;

    const float* Aptr = (MODE == 3) ? (const float*)d_S : A0;
    const int bn_ = tid >> 2, bkq = (tid & 3) * 4;
    const int jg = j0 + bn_;
    const float* wrow;
    if (MODE == 2) wrow = (jg < 128) ? (B0 + (size_t)jg*DIM) : (B1 + (size_t)(jg-128)*DIM);
    else if (MODE == 3) wrow = (const float*)d_Wc + (size_t)jg*DIM;
    else wrow = B0 + (size_t)jg*DIM;

    const int am = tid >> 1, akq = (tid & 1) * 8;       // MODE 2/3 A staging
    const int kk = tid >> 4, pg = tid & 15;             // MODE 1 A staging
    const int mga = m0 + am;

    const unsigned as_base = smem_addr(&As[0][0]);
    const unsigned bs_base = smem_addr(&Bs[0][0]);
    const int bit3 = (lane >> 3) & 1, bit4 = lane >> 4;
    // non-trans A lane offset (fp16 units -> bytes)
    const unsigned aoffs = (unsigned)(((mw + (lane & 7) + bit3*8) * AST + bit4*8) << 1);
    // trans A (MODE 1) lane offset
    const unsigned atoffs = (unsigned)((((lane & 7) + bit4*8) * MSTR + mw + bit3*8) << 1);
    // B lane offset
    const unsigned boffs = (unsigned)(((nw + (lane & 7) + bit3*8) * BST + bit4*8) << 1);

    float c_[2][4][4];
    #pragma unroll
    for (int mi = 0; mi < 2; mi++)
        #pragma unroll
        for (int ni = 0; ni < 4; ni++)
            #pragma unroll
            for (int r = 0; r < 4; r++) c_[mi][ni][r] = 0.f;

    float4 pa0, pa1, pb;
    auto zero4 = make_float4(0.f, 0.f, 0.f, 0.f);
    #define LOAD_CHUNK(k0) do {                                                      \
        if (MODE == 1) {                                                             \
            const float* src = A0 + ((size_t)(camI*DIM + (k0) + kk))*HWF + p0 + pg*8;\
            pa0 = *(const float4*)src; pa1 = *(const float4*)(src + 4);              \
        } else {                                                                     \
            pa0 = zero4; pa1 = zero4;                                                \
            if (mga < Mrows) {                                                       \
                pa0 = *(const float4*)(Aptr + (size_t)mga*DIM + (k0) + akq);         \
                pa1 = *(const float4*)(Aptr + (size_t)mga*DIM + (k0) + akq + 4);     \
                if (MODE == 2) {                                                     \
                    float4 q0 = *(const float4*)(A1 + (size_t)mga*DIM + (k0) + akq); \
                    float4 q1 = *(const float4*)(A1 + (size_t)mga*DIM + (k0) + akq+4);\
                    pa0.x+=q0.x; pa0.y+=q0.y; pa0.z+=q0.z; pa0.w+=q0.w;              \
                    pa1.x+=q1.x; pa1.y+=q1.y; pa1.z+=q1.z; pa1.w+=q1.w;              \
                }                                                                    \
            }                                                                        \
        }                                                                            \
        pb = *(const float4*)(wrow + (k0) + bkq);                                    \
    } while (0)

    #define STORE_CHUNK(buf) do {                                                   \
        uint4 ha = make_uint4(p2(pa0.x,pa0.y), p2(pa0.z,pa0.w),                     \
                              p2(pa1.x,pa1.y), p2(pa1.z,pa1.w));                    \
        if (MODE == 1) *(uint4*)&As[buf][kk*MSTR + pg*8] = ha;                      \
        else           *(uint4*)&As[buf][am*AST + akq]   = ha;                      \
        *(uint2*)&Bs[buf][bn_*BST + bkq] = make_uint2(p2(pb.x,pb.y), p2(pb.z,pb.w));\
    } while (0)

    LOAD_CHUNK(0);
    STORE_CHUNK(0);
    __syncthreads();

    #pragma unroll 1
    for (int cch = 0; cch < 16; cch++) {
        const int buf = cch & 1;
        if (cch < 15) LOAD_CHUNK((cch + 1) * 16);
        const unsigned aoff = as_base + (unsigned)buf * 6144u;
        const unsigned boff = bs_base + (unsigned)buf * 3072u;
        unsigned a[2][4], b[2][4];
        if (MODE == 1) {
            #pragma unroll
            for (int mi = 0; mi < 2; mi++) ldmx4t(a[mi], aoff + atoffs + mi*32u);
        } else {
            #pragma unroll
            for (int mi = 0; mi < 2; mi++) ldmx4(a[mi], aoff + aoffs + mi*768u);
        }
        #pragma unroll
        for (int np = 0; np < 2; np++) ldmx4(b[np], boff + boffs + np*768u);
        #pragma unroll
        for (int mi = 0; mi < 2; mi++) {
            mma16816(c_[mi][0], a[mi], b[0][0], b[0][2]);
            mma16816(c_[mi][1], a[mi], b[0][1], b[0][3]);
            mma16816(c_[mi][2], a[mi], b[1][0], b[1][2]);
            mma16816(c_[mi][3], a[mi], b[1][1], b[1][3]);
        }
        if (cch < 15) STORE_CHUNK(buf ^ 1);
        __syncthreads();
    }

    // ---- epilogue (C fragment layout identical to tf32 m16n8) ----
    #pragma unroll
    for (int mi = 0; mi < 2; mi++) {
        #pragma unroll
        for (int ni = 0; ni < 4; ni++) {
            const int jc = j0 + nw + ni*8 + 2*t;
            const int r0 = mw + mi*16 + g;
            const float* cr = c_[mi][ni];
            if (MODE == 1) {
                const int h = jc >> 5, hd = jc & 31;
                float b0 = d_bias2[camI*DIM + jc], b1 = d_bias2[camI*DIM + jc + 1];
                __half* o0 = d_value + ((size_t)(camI*NH + h)*HWF + p0 + r0)*HD + hd;
                __half* o1 = o0 + 8*HD;
                *(__half2*)o0 = __floats2half2_rn(cr[0] + b0, cr[1] + b1);
                *(__half2*)o1 = __floats2half2_rn(cr[2] + b0, cr[3] + b1);
            } else if (MODE == 2) {
                float b0, b1;
                if (jc < 128) { b0 = bias0[jc]; b1 = bias0[jc+1]; }
                else          { b0 = bias1[jc-128]; b1 = bias1[jc-127]; }
                int mr0 = m0 + r0, mr1 = mr0 + 8;
                if (mr0 < MROWS)
                    *(float2*)&d_offattn[(size_t)mr0*OAC + jc] = make_float2(cr[0]+b0, cr[1]+b1);
                if (mr1 < MROWS)
                    *(float2*)&d_offattn[(size_t)mr1*OAC + jc] = make_float2(cr[2]+b0, cr[3]+b1);
            } else {
                float b0 = bias0[jc] , b1 = bias0[jc+1];
                float e0 = d_bi2[jc], e1 = d_bi2[jc+1];
                int mr0 = m0 + r0, mr1 = mr0 + 8;
                if (mr0 < QN) {
                    float gf = d_gflag[mr0];
                    *(float2*)&C[(size_t)mr0*DIM + jc] =
                        make_float2(cr[0] + b0 + gf*e0, cr[1] + b1 + gf*e1);
                }
                if (mr1 < QN) {
                    float gf = d_gflag[mr1];
                    *(float2*)&C[(size_t)mr1*DIM + jc] =
                        make_float2(cr[2] + b0 + gf*e0, cr[3] + b1 + gf*e1);
                }
            }
        }
    }
    #undef LOAD_CHUNK
    #undef STORE_CHUNK
}

// ---------------- sampling: compute-once, shuffle-results ----------------
__global__ __launch_bounds__(256) void sample_kernel(const float* __restrict__ ref,
                                                     const void* __restrict__ mask) {
    const int q = blockIdx.x;
    const int tid = threadIdx.x;
    const int h = tid>>5, l = tid&31;
    const int c8 = l&7;
    const int ox = (l>>3)&1, oy = l>>4;
    __shared__ float s_hit[NCAM];
    __shared__ float s_inv, s_g;
    if (tid < NCAM) {
        const int mode = d_mask_mode;
        size_t base = (size_t)(tid*QN + q)*8;
        int hit = mask_elem(mask, base+0, mode) | mask_elem(mask, base+2, mode) |
                  mask_elem(mask, base+4, mode) | mask_elem(mask, base+6, mode);
        s_hit[tid] = hit ? 1.f : 0.f;
    }
    __syncthreads();
    if (tid == 0) {
        float c = s_hit[0]+s_hit[1]+s_hit[2]+s_hit[3]+s_hit[4]+s_hit[5];
        s_g = (c > 0.f) ? 1.f : 0.f;
        s_inv = 1.f / fmaxf(c, 1.f);
    }
    __syncthreads();
    float ax=0.f, ay=0.f, az=0.f, aw=0.f;
    for (int camI = 0; camI < NCAM; camI++) {
        if (s_hit[camI] == 0.f) continue;
        const float* row = d_offattn + (size_t)(camI*QN + q)*OAC;
        float logit = row[128 + h*8 + c8];
        float ofx   = row[h*16 + c8*2];
        float ofy   = row[h*16 + c8*2 + 1];
        const float* rp = ref + ((size_t)(camI*QN + q)*4 + (c8&3))*2;
        float rx = rp[0], ry = rp[1];
        float mx = logit;
        mx = fmaxf(mx, __shfl_xor_sync(0xffffffffu, mx, 1, 8));
        mx = fmaxf(mx, __shfl_xor_sync(0xffffffffu, mx, 2, 8));
        mx = fmaxf(mx, __shfl_xor_sync(0xffffffffu, mx, 4, 8));
        float e = __expf(logit - mx);
        float sm = e;
        sm += __shfl_xor_sync(0xffffffffu, sm, 1, 8);
        sm += __shfl_xor_sync(0xffffffffu, sm, 2, 8);
        sm += __shfl_xor_sync(0xffffffffu, sm, 4, 8);
        float w = e / sm;
        float x = fmaf(rx, (float)WFv, ofx) - 0.5f;
        float y = fmaf(ry, (float)HFv, ofy) - 0.5f;
        float xf = floorf(x), yf = floorf(y);
        float dx = x - xf, dy = y - yf;
        int xi = (int)xf + ox;
        int yi = (int)yf + oy;
        float wx = ox ? dx : (1.f - dx);
        float wy = oy ? dy : (1.f - dy);
        bool valid = (xi >= 0) && (xi < WFv) && (yi >= 0) && (yi < HFv);
        float wc = valid ? (w*wx*wy) : 0.f;
        int pix = min(max(yi,0),HFv-1)*WFv + min(max(xi,0),WFv-1);
        const __half* vb = d_value + (size_t)(camI*NH + h)*HWF*HD + c8*4;
        #pragma unroll
        for (int p = 0; p < 8; p++) {
            float wcp = __shfl_sync(0xffffffffu, wc,  p, 8);
            int  pixp = __shfl_sync(0xffffffffu, pix, p, 8);
            uint2 raw = *(const uint2*)(vb + (size_t)pixp*HD);
            float2 f0 = __half22float2(*(__half2*)&raw.x);
            float2 f1 = __half22float2(*(__half2*)&raw.y);
            ax = fmaf(wcp, f0.x, ax); ay = fmaf(wcp, f0.y, ay);
            az = fmaf(wcp, f1.x, az); aw = fmaf(wcp, f1.y, aw);
        }
    }
    ax += __shfl_xor_sync(0xffffffffu, ax, 8);  ax += __shfl_xor_sync(0xffffffffu, ax, 16);
    ay += __shfl_xor_sync(0xffffffffu, ay, 8);  ay += __shfl_xor_sync(0xffffffffu, ay, 16);
    az += __shfl_xor_sync(0xffffffffu, az, 8);  az += __shfl_xor_sync(0xffffffffu, az, 16);
    aw += __shfl_xor_sync(0xffffffffu, aw, 8);  aw += __shfl_xor_sync(0xffffffffu, aw, 16);
    if (l < 8) {
        float inv = s_inv;
        float4 o = make_float4(ax*inv, ay*inv, az*inv, aw*inv);
        *(float4*)&d_S[(size_t)q*DIM + h*HD + c8*4] = o;
    }
    if (tid == 0) d_gflag[q] = s_g;
}

// ---------------- launch ----------------
extern "C" void kernel_launch(void* const* d_in, const int* in_sizes, int n_in,
                              void* d_out, int out_size) {
    const float* queries = (const float*)d_in[0];
    const float* pos     = (const float*)d_in[1];
    const float* lvl     = (const float*)d_in[2];
    const float* camemb  = (const float*)d_in[3];
    const float* feat    = (const float*)d_in[4];
    const float* ref     = (const float*)d_in[5];
    const void*  mask    = (const void*)d_in[6];
    const float* W_value = (const float*)d_in[7];
    const float* b_value = (const float*)d_in[8];
    const float* W_off   = (const float*)d_in[9];
    const float* b_off   = (const float*)d_in[10];
    const float* W_attn  = (const float*)d_in[11];
    const float* b_attn  = (const float*)d_in[12];
    const float* W_inner = (const float*)d_in[13];
    const float* b_inner = (const float*)d_in[14];
    const float* W_out   = (const float*)d_in[15];
    const float* b_out   = (const float*)d_in[16];
    float* out = (float*)d_out;

    prep_a<<<NCAM + 1, DIM>>>(lvl, camemb, W_value, b_value, (const unsigned int*)mask);
    gemm_tc<1><<<dim3(4, 132), 256>>>(feat, nullptr, W_value, nullptr,
                                      nullptr, nullptr, nullptr);
    gemm_tc<2><<<dim3(3, 469), 256>>>(queries, pos, W_off, W_attn,
                                      b_off, b_attn, nullptr);
    sample_kernel<<<QN, 256>>>(ref, mask);
    prep_b<<<DIM + 1, DIM>>>(W_out, W_inner, b_inner);
    gemm_tc<3><<<dim3(4, 79), 256>>>(nullptr, nullptr, nullptr, nullptr,
                                     b_out, nullptr, out);
    (void)in_sizes; (void)n_in; (void)out_size;
}

// round 10
// speedup vs baseline: 1.3621x; 1.0397x over previous
#include <cuda_runtime.h>
#include <cuda_fp16.h>
#include <cstdint>

#define QN   10000
#define NCAM 6
#define DIM  256
#define HWF  2816     // 32*88
#define NH   8
#define HD   32
#define HFv  32
#define WFv  88
#define MROWS (NCAM*QN)   // 60000
#define OAC  192          // 128 offsets + 64 attn logits

// ---------------- scratch ----------------
__device__ __half d_value[NCAM*NH*HWF*HD];  // (cam, head, hw, hd) fp16
__device__ float d_offattn[(size_t)MROWS*OAC];
__device__ float d_S[(size_t)QN*DIM];
__device__ float d_gflag[QN];
__device__ float d_bias2[NCAM*DIM];
__device__ float d_Wc[DIM*DIM];             // W_out @ W_inner
__device__ float d_bi2[DIM];                // W_out @ b_inner
__device__ int   d_mask_mode;               // 0=u8, 1=i32, 2=f32

__device__ __forceinline__ int mask_elem(const void* mask, size_t idx, int mode) {
    if (mode == 0) return ((const unsigned char*)mask)[idx] != 0;
    if (mode == 1) return ((const int*)mask)[idx] != 0;
    return ((const float*)mask)[idx] != 0.f;
}

// ---------------- prep A: bias2 (blocks 0..5) + mask detect (block 6) ----------------
__global__ void prep_a(const float* __restrict__ lvl, const float* __restrict__ camemb,
                       const float* __restrict__ Wv, const float* __restrict__ bv,
                       const unsigned int* __restrict__ mk) {
    int c = blockIdx.x, j = threadIdx.x;
    if (c == NCAM) {
        if (j < 32) {
            bool f = false, multi = false;
            for (int i = j; i < 256; i += 32) {
                unsigned int w = mk[i];
                f |= (w == 0x3F800000u);
                multi |= (w != 0x3F800000u && w > 1u);
            }
            unsigned bf = __ballot_sync(0xffffffffu, f), bm = __ballot_sync(0xffffffffu, multi);
            if (j == 0) d_mask_mode = bf ? 2 : (bm ? 0 : 1);
        }
        return;
    }
    __shared__ float e[DIM];
    e[j] = lvl[j] + camemb[c*DIM + j];
    __syncthreads();
    const float4* w4 = (const float4*)(Wv + (size_t)j*DIM);
    const float4* e4 = (const float4*)e;
    float s = bv[j];
    #pragma unroll 8
    for (int k = 0; k < DIM/4; k++) {
        float4 w = w4[k]; float4 ev = e4[k];
        s += w.x*ev.x + w.y*ev.y + w.z*ev.z + w.w*ev.w;
    }
    d_bias2[c*DIM + j] = s;
}

// ---------------- prep B: Wc (blocks 0..255) + bi2 (block 256) ----------------
__global__ void prep_b(const float* __restrict__ Wo, const float* __restrict__ Wi,
                       const float* __restrict__ bi) {
    int i = blockIdx.x, j = threadIdx.x;
    if (i == DIM) {
        int w = j >> 5, l = j & 31;
        for (int ii = w; ii < DIM; ii += 8) {
            float s = 0.f;
            #pragma unroll
            for (int t = 0; t < 8; t++) {
                int k = l + 32*t;
                s += Wo[(size_t)ii*DIM + k] * bi[k];
            }
            #pragma unroll
            for (int o = 16; o; o >>= 1) s += __shfl_xor_sync(0xffffffffu, s, o);
            if (l == 0) d_bi2[ii] = s;
        }
        return;
    }
    __shared__ float wo[DIM];
    wo[j] = Wo[(size_t)i*DIM + j];
    __syncthreads();
    float s = 0.f;
    #pragma unroll 8
    for (int k = 0; k < DIM; k++) s += wo[k] * Wi[(size_t)k*DIM + j];
    d_Wc[(size_t)i*DIM + j] = s;
}

// ---------------- fp16 mma.sync m16n8k16 GEMM core ----------------
#define AST 24
#define MSTR 136
#define BST 24

__device__ __forceinline__ unsigned p2(float x, float y) {
    __half2 h = __floats2half2_rn(x, y);
    return *(unsigned*)&h;
}
__device__ __forceinline__ void mma16816(float* c, const unsigned* a, unsigned b0, unsigned b1) {
    asm volatile("mma.sync.aligned.m16n8k16.row.col.f32.f16.f16.f32 "
        "{%0,%1,%2,%3}, {%4,%5,%6,%7}, {%8,%9}, {%0,%1,%2,%3};"
        : "+f"(c[0]), "+f"(c[1]), "+f"(c[2]), "+f"(c[3])
        : "r"(a[0]), "r"(a[1]), "r"(a[2]), "r"(a[3]), "r"(b0), "r"(b1));
}
__device__ __forceinline__ void ldmx4(unsigned* r, unsigned addr) {
    asm volatile("ldmatrix.sync.aligned.m8n8.x4.shared.b16 {%0,%1,%2,%3}, [%4];"
        : "=r"(r[0]), "=r"(r[1]), "=r"(r[2]), "=r"(r[3]) : "r"(addr));
}
__device__ __forceinline__ void ldmx4t(unsigned* r, unsigned addr) {
    asm volatile("ldmatrix.sync.aligned.m8n8.x4.trans.shared.b16 {%0,%1,%2,%3}, [%4];"
        : "=r"(r[0]), "=r"(r[1]), "=r"(r[2]), "=r"(r[3]) : "r"(addr));
}
__device__ __forceinline__ unsigned smem_addr(const void* p) {
    return (unsigned)__cvta_generic_to_shared(p);
}

template<int MODE>
__global__ __launch_bounds__(256, 2) void gemm_tc(
    const float* __restrict__ A0, const float* __restrict__ A1,
    const float* __restrict__ B0, const float* __restrict__ B1,
    const float* __restrict__ bias0, const float* __restrict__ bias1,
    float* __restrict__ C)
{
    __shared__ __half As[2][3072];
    __shared__ __half Bs[2][1536];
    const int tid = threadIdx.x;
    const int lane = tid & 31, wid = tid >> 5;
    const int mw = (wid & 3) * 32, nw = (wid >> 2) * 32;
    const int g = lane >> 2, t = lane & 3;
    const int j0 = blockIdx.x * 64;

    int camI = 0, p0 = 0, m0 = 0;
    if (MODE == 1) { camI = blockIdx.y / 22; p0 = (blockIdx.y % 22) * 128; }
    else m0 = blockIdx.y * 128;
    const int Mrows = (MODE == 2) ? MROWS : QN;

    const float* Aptr = (MODE == 3) ? (const float*)d_S : A0;
    const int bn_ = tid >> 2, bkq = (tid & 3) * 4;
    const int jg = j0 + bn_;
    const float* wrow;
    if (MODE == 2) wrow = (jg < 128) ? (B0 + (size_t)jg*DIM) : (B1 + (size_t)(jg-128)*DIM);
    else if (MODE == 3) wrow = (const float*)d_Wc + (size_t)jg*DIM;
    else wrow = B0 + (size_t)jg*DIM;

    const int am = tid >> 1, akq = (tid & 1) * 8;
    const int kk = tid >> 4, pg = tid & 15;
    const int mga = m0 + am;

    const unsigned as_base = smem_addr(&As[0][0]);
    const unsigned bs_base = smem_addr(&Bs[0][0]);
    const int bit3 = (lane >> 3) & 1, bit4 = lane >> 4;
    const unsigned aoffs = (unsigned)(((mw + (lane & 7) + bit3*8) * AST + bit4*8) << 1);
    const unsigned atoffs = (unsigned)((((lane & 7) + bit4*8) * MSTR + mw + bit3*8) << 1);
    const unsigned boffs = (unsigned)(((nw + (lane & 7) + bit3*8) * BST + bit4*8) << 1);

    float c_[2][4][4];
    #pragma unroll
    for (int mi = 0; mi < 2; mi++)
        #pragma unroll
        for (int ni = 0; ni < 4; ni++)
            #pragma unroll
            for (int r = 0; r < 4; r++) c_[mi][ni][r] = 0.f;

    float4 pa0, pa1, pb;
    auto zero4 = make_float4(0.f, 0.f, 0.f, 0.f);
    #define LOAD_CHUNK(k0) do {                                                      \
        if (MODE == 1) {                                                             \
            const float* src = A0 + ((size_t)(camI*DIM + (k0) + kk))*HWF + p0 + pg*8;\
            pa0 = *(const float4*)src; pa1 = *(const float4*)(src + 4);              \
        } else {                                                                     \
            pa0 = zero4; pa1 = zero4;                                                \
            if (mga < Mrows) {                                                       \
                pa0 = *(const float4*)(Aptr + (size_t)mga*DIM + (k0) + akq);         \
                pa1 = *(const float4*)(Aptr + (size_t)mga*DIM + (k0) + akq + 4);     \
                if (MODE == 2) {                                                     \
                    float4 q0 = *(const float4*)(A1 + (size_t)mga*DIM + (k0) + akq); \
                    float4 q1 = *(const float4*)(A1 + (size_t)mga*DIM + (k0) + akq+4);\
                    pa0.x+=q0.x; pa0.y+=q0.y; pa0.z+=q0.z; pa0.w+=q0.w;              \
                    pa1.x+=q1.x; pa1.y+=q1.y; pa1.z+=q1.z; pa1.w+=q1.w;              \
                }                                                                    \
            }                                                                        \
        }                                                                            \
        pb = *(const float4*)(wrow + (k0) + bkq);                                    \
    } while (0)

    #define STORE_CHUNK(buf) do {                                                   \
        uint4 ha = make_uint4(p2(pa0.x,pa0.y), p2(pa0.z,pa0.w),                     \
                              p2(pa1.x,pa1.y), p2(pa1.z,pa1.w));                    \
        if (MODE == 1) *(uint4*)&As[buf][kk*MSTR + pg*8] = ha;                      \
        else           *(uint4*)&As[buf][am*AST + akq]   = ha;                      \
        *(uint2*)&Bs[buf][bn_*BST + bkq] = make_uint2(p2(pb.x,pb.y), p2(pb.z,pb.w));\
    } while (0)

    LOAD_CHUNK(0);
    STORE_CHUNK(0);
    __syncthreads();

    #pragma unroll 1
    for (int cch = 0; cch < 16; cch++) {
        const int buf = cch & 1;
        if (cch < 15) LOAD_CHUNK((cch + 1) * 16);
        const unsigned aoff = as_base + (unsigned)buf * 6144u;
        const unsigned boff = bs_base + (unsigned)buf * 3072u;
        unsigned a[2][4], b[2][4];
        if (MODE == 1) {
            #pragma unroll
            for (int mi = 0; mi < 2; mi++) ldmx4t(a[mi], aoff + atoffs + mi*32u);
        } else {
            #pragma unroll
            for (int mi = 0; mi < 2; mi++) ldmx4(a[mi], aoff + aoffs + mi*768u);
        }
        #pragma unroll
        for (int np = 0; np < 2; np++) ldmx4(b[np], boff + boffs + np*768u);
        #pragma unroll
        for (int mi = 0; mi < 2; mi++) {
            mma16816(c_[mi][0], a[mi], b[0][0], b[0][2]);
            mma16816(c_[mi][1], a[mi], b[0][1], b[0][3]);
            mma16816(c_[mi][2], a[mi], b[1][0], b[1][2]);
            mma16816(c_[mi][3], a[mi], b[1][1], b[1][3]);
        }
        if (cch < 15) STORE_CHUNK(buf ^ 1);
        __syncthreads();
    }

    // ---- epilogue ----
    #pragma unroll
    for (int mi = 0; mi < 2; mi++) {
        #pragma unroll
        for (int ni = 0; ni < 4; ni++) {
            const int jc = j0 + nw + ni*8 + 2*t;
            const int r0 = mw + mi*16 + g;
            const float* cr = c_[mi][ni];
            if (MODE == 1) {
                const int h = jc >> 5, hd = jc & 31;
                float b0 = d_bias2[camI*DIM + jc], b1 = d_bias2[camI*DIM + jc + 1];
                __half* o0 = d_value + ((size_t)(camI*NH + h)*HWF + p0 + r0)*HD + hd;
                __half* o1 = o0 + 8*HD;
                *(__half2*)o0 = __floats2half2_rn(cr[0] + b0, cr[1] + b1);
                *(__half2*)o1 = __floats2half2_rn(cr[2] + b0, cr[3] + b1);
            } else if (MODE == 2) {
                float b0, b1;
                if (jc < 128) { b0 = bias0[jc]; b1 = bias0[jc+1]; }
                else          { b0 = bias1[jc-128]; b1 = bias1[jc-127]; }
                int mr0 = m0 + r0, mr1 = mr0 + 8;
                if (mr0 < MROWS)
                    *(float2*)&d_offattn[(size_t)mr0*OAC + jc] = make_float2(cr[0]+b0, cr[1]+b1);
                if (mr1 < MROWS)
                    *(float2*)&d_offattn[(size_t)mr1*OAC + jc] = make_float2(cr[2]+b0, cr[3]+b1);
            } else {
                float b0 = bias0[jc] , b1 = bias0[jc+1];
                float e0 = d_bi2[jc], e1 = d_bi2[jc+1];
                int mr0 = m0 + r0, mr1 = mr0 + 8;
                if (mr0 < QN) {
                    float gf = d_gflag[mr0];
                    *(float2*)&C[(size_t)mr0*DIM + jc] =
                        make_float2(cr[0] + b0 + gf*e0, cr[1] + b1 + gf*e1);
                }
                if (mr1 < QN) {
                    float gf = d_gflag[mr1];
                    *(float2*)&C[(size_t)mr1*DIM + jc] =
                        make_float2(cr[2] + b0 + gf*e0, cr[3] + b1 + gf*e1);
                }
            }
        }
    }
    #undef LOAD_CHUNK
    #undef STORE_CHUNK
}

// ---------------- sampling v3: 16B gathers, 2 points/iter ----------------
// compute phase: lane = oy(b4)|ox(b3)|point(b2..0) -> own (pix, wc)
// gather phase:  lane = psel(b4)|corner(b3..2)|oct(b1..0); 4 iters cover 8 points
__global__ __launch_bounds__(256) void sample_kernel(const float* __restrict__ ref,
                                                     const void* __restrict__ mask) {
    const int q = blockIdx.x;
    const int tid = threadIdx.x;
    const int h = tid>>5, l = tid&31;
    const int c8 = l&7;
    const int ox = (l>>3)&1, oy = l>>4;
    // gather-phase roles
    const int oct = l&3, corg = (l>>2)&3, psel = l>>4;
    const int oxg = corg&1, oyg = corg>>1;
    const int srcl_base = oyg*16 + oxg*8 + psel;   // + 2*pp at use
    __shared__ float s_hit[NCAM];
    __shared__ float s_inv, s_g;
    if (tid < NCAM) {
        const int mode = d_mask_mode;
        size_t base = (size_t)(tid*QN + q)*8;
        int hit = mask_elem(mask, base+0, mode) | mask_elem(mask, base+2, mode) |
                  mask_elem(mask, base+4, mode) | mask_elem(mask, base+6, mode);
        s_hit[tid] = hit ? 1.f : 0.f;
    }
    __syncthreads();
    if (tid == 0) {
        float c = s_hit[0]+s_hit[1]+s_hit[2]+s_hit[3]+s_hit[4]+s_hit[5];
        s_g = (c > 0.f) ? 1.f : 0.f;
        s_inv = 1.f / fmaxf(c, 1.f);
    }
    __syncthreads();
    float acc[8];
    #pragma unroll
    for (int i = 0; i < 8; i++) acc[i] = 0.f;

    for (int camI = 0; camI < NCAM; camI++) {
        if (s_hit[camI] == 0.f) continue;
        const float* row = d_offattn + (size_t)(camI*QN + q)*OAC;
        float logit = row[128 + h*8 + c8];
        float2 of = *(const float2*)(row + h*16 + c8*2);
        const float* rp = ref + ((size_t)(camI*QN + q)*4 + (c8&3))*2;
        float rx = rp[0], ry = rp[1];
        // softmax over 8 points (no max-sub; logits are O(few))
        float e = __expf(logit);
        float sm = e;
        sm += __shfl_xor_sync(0xffffffffu, sm, 1, 8);
        sm += __shfl_xor_sync(0xffffffffu, sm, 2, 8);
        sm += __shfl_xor_sync(0xffffffffu, sm, 4, 8);
        float w = __fdividef(e, sm);
        // own point's position/weight at own corner
        float x = fmaf(rx, (float)WFv, of.x) - 0.5f;
        float y = fmaf(ry, (float)HFv, of.y) - 0.5f;
        float xf = floorf(x), yf = floorf(y);
        float dx = x - xf, dy = y - yf;
        int xi = (int)xf + ox;
        int yi = (int)yf + oy;
        float wx = ox ? dx : (1.f - dx);
        float wy = oy ? dy : (1.f - dy);
        bool valid = (xi >= 0) && (xi < WFv) && (yi >= 0) && (yi < HFv);
        float wc = valid ? (w*wx*wy) : 0.f;
        int pix = min(max(yi,0),HFv-1)*WFv + min(max(xi,0),WFv-1);
        const __half* vh = d_value + (size_t)(camI*NH + h)*HWF*HD + oct*8;
        #pragma unroll
        for (int pp = 0; pp < 4; pp++) {
            int srcl = srcl_base + 2*pp;
            float wcp = __shfl_sync(0xffffffffu, wc,  srcl);
            int  pixp = __shfl_sync(0xffffffffu, pix, srcl);
            uint4 raw = *(const uint4*)(vh + (size_t)pixp*HD);
            float2 f0 = __half22float2(*(__half2*)&raw.x);
            float2 f1 = __half22float2(*(__half2*)&raw.y);
            float2 f2 = __half22float2(*(__half2*)&raw.z);
            float2 f3 = __half22float2(*(__half2*)&raw.w);
            acc[0] = fmaf(wcp, f0.x, acc[0]); acc[1] = fmaf(wcp, f0.y, acc[1]);
            acc[2] = fmaf(wcp, f1.x, acc[2]); acc[3] = fmaf(wcp, f1.y, acc[3]);
            acc[4] = fmaf(wcp, f2.x, acc[4]); acc[5] = fmaf(wcp, f2.y, acc[5]);
            acc[6] = fmaf(wcp, f3.x, acc[6]); acc[7] = fmaf(wcp, f3.y, acc[7]);
        }
    }
    // reduce over corner bits (2,3) and point-half bit (4)
    #pragma unroll
    for (int i = 0; i < 8; i++) {
        acc[i] += __shfl_xor_sync(0xffffffffu, acc[i], 4);
        acc[i] += __shfl_xor_sync(0xffffffffu, acc[i], 8);
        acc[i] += __shfl_xor_sync(0xffffffffu, acc[i], 16);
    }
    if (l < 4) {
        float inv = s_inv;
        float* o = d_S + (size_t)q*DIM + h*HD + l*8;
        *(float4*)o       = make_float4(acc[0]*inv, acc[1]*inv, acc[2]*inv, acc[3]*inv);
        *(float4*)(o + 4) = make_float4(acc[4]*inv, acc[5]*inv, acc[6]*inv, acc[7]*inv);
    }
    if (tid == 0) d_gflag[q] = s_g;
}

// ---------------- launch ----------------
extern "C" void kernel_launch(void* const* d_in, const int* in_sizes, int n_in,
                              void* d_out, int out_size) {
    const float* queries = (const float*)d_in[0];
    const float* pos     = (const float*)d_in[1];
    const float* lvl     = (const float*)d_in[2];
    const float* camemb  = (const float*)d_in[3];
    const float* feat    = (const float*)d_in[4];
    const float* ref     = (const float*)d_in[5];
    const void*  mask    = (const void*)d_in[6];
    const float* W_value = (const float*)d_in[7];
    const float* b_value = (const float*)d_in[8];
    const float* W_off   = (const float*)d_in[9];
    const float* b_off   = (const float*)d_in[10];
    const float* W_attn  = (const float*)d_in[11];
    const float* b_attn  = (const float*)d_in[12];
    const float* W_inner = (const float*)d_in[13];
    const float* b_inner = (const float*)d_in[14];
    const float* W_out   = (const float*)d_in[15];
    const float* b_out   = (const float*)d_in[16];
    float* out = (float*)d_out;

    prep_a<<<NCAM + 1, DIM>>>(lvl, camemb, W_value, b_value, (const unsigned int*)mask);
    prep_b<<<DIM + 1, DIM>>>(W_out, W_inner, b_inner);
    gemm_tc<1><<<dim3(4, 132), 256>>>(feat, nullptr, W_value, nullptr,
                                      nullptr, nullptr, nullptr);
    gemm_tc<2><<<dim3(3, 469), 256>>>(queries, pos, W_off, W_attn,
                                      b_off, b_attn, nullptr);
    sample_kernel<<<QN, 256>>>(ref, mask);
    gemm_tc<3><<<dim3(4, 79), 256>>>(nullptr, nullptr, nullptr, nullptr,
                                     b_out, nullptr, out);
    (void)in_sizes; (void)n_in; (void)out_size;
}

// round 11
// speedup vs baseline: 1.4972x; 1.0992x over previous
#include <cuda_runtime.h>
#include <cuda_fp16.h>
#include <cstdint>

#define QN   10000
#define NCAM 6
#define DIM  256
#define HWF  2816     // 32*88
#define NH   8
#define HD   32
#define HFv  32
#define WFv  88
#define MROWS (NCAM*QN)   // 60000
#define OAC  192          // 128 offsets + 64 attn logits

// ---------------- scratch ----------------
__device__ __half d_value[NCAM*NH*HWF*HD];  // (cam, head, hw, hd) fp16
__device__ float d_offattn[(size_t)MROWS*OAC];
__device__ float d_S[(size_t)QN*DIM];
__device__ float d_gflag[QN];
__device__ float d_bias2[NCAM*DIM];
__device__ float d_Wc[DIM*DIM];             // W_out @ W_inner
__device__ float d_bi2[DIM];                // W_out @ b_inner
__device__ int   d_mask_mode;               // 0=u8, 1=i32, 2=f32

__device__ __forceinline__ int mask_elem(const void* mask, size_t idx, int mode) {
    if (mode == 0) return ((const unsigned char*)mask)[idx] != 0;
    if (mode == 1) return ((const int*)mask)[idx] != 0;
    return ((const float*)mask)[idx] != 0.f;
}

// ---------------- prep A: bias2 (blocks 0..5) + mask detect (block 6) ----------------
__global__ void prep_a(const float* __restrict__ lvl, const float* __restrict__ camemb,
                       const float* __restrict__ Wv, const float* __restrict__ bv,
                       const unsigned int* __restrict__ mk) {
    int c = blockIdx.x, j = threadIdx.x;
    if (c == NCAM) {
        if (j < 32) {
            bool f = false, multi = false;
            for (int i = j; i < 256; i += 32) {
                unsigned int w = mk[i];
                f |= (w == 0x3F800000u);
                multi |= (w != 0x3F800000u && w > 1u);
            }
            unsigned bf = __ballot_sync(0xffffffffu, f), bm = __ballot_sync(0xffffffffu, multi);
            if (j == 0) d_mask_mode = bf ? 2 : (bm ? 0 : 1);
        }
        return;
    }
    __shared__ float e[DIM];
    e[j] = lvl[j] + camemb[c*DIM + j];
    __syncthreads();
    const float4* w4 = (const float4*)(Wv + (size_t)j*DIM);
    const float4* e4 = (const float4*)e;
    float s = bv[j];
    #pragma unroll 8
    for (int k = 0; k < DIM/4; k++) {
        float4 w = w4[k]; float4 ev = e4[k];
        s += w.x*ev.x + w.y*ev.y + w.z*ev.z + w.w*ev.w;
    }
    d_bias2[c*DIM + j] = s;
}

// ---------------- prep B: Wc (blocks 0..255) + bi2 (block 256) ----------------
__global__ void prep_b(const float* __restrict__ Wo, const float* __restrict__ Wi,
                       const float* __restrict__ bi) {
    int i = blockIdx.x, j = threadIdx.x;
    if (i == DIM) {
        int w = j >> 5, l = j & 31;
        for (int ii = w; ii < DIM; ii += 8) {
            float s = 0.f;
            #pragma unroll
            for (int t = 0; t < 8; t++) {
                int k = l + 32*t;
                s += Wo[(size_t)ii*DIM + k] * bi[k];
            }
            #pragma unroll
            for (int o = 16; o; o >>= 1) s += __shfl_xor_sync(0xffffffffu, s, o);
            if (l == 0) d_bi2[ii] = s;
        }
        return;
    }
    __shared__ float wo[DIM];
    wo[j] = Wo[(size_t)i*DIM + j];
    __syncthreads();
    float s = 0.f;
    #pragma unroll 8
    for (int k = 0; k < DIM; k++) s += wo[k] * Wi[(size_t)k*DIM + j];
    d_Wc[(size_t)i*DIM + j] = s;
}

// ---------------- fp16 mma common ----------------
#define AST 24
#define MSTR 136
#define BST 24

__device__ __forceinline__ unsigned p2(float x, float y) {
    __half2 h = __floats2half2_rn(x, y);
    return *(unsigned*)&h;
}
__device__ __forceinline__ void mma16816(float* c, const unsigned* a, unsigned b0, unsigned b1) {
    asm volatile("mma.sync.aligned.m16n8k16.row.col.f32.f16.f16.f32 "
        "{%0,%1,%2,%3}, {%4,%5,%6,%7}, {%8,%9}, {%0,%1,%2,%3};"
        : "+f"(c[0]), "+f"(c[1]), "+f"(c[2]), "+f"(c[3])
        : "r"(a[0]), "r"(a[1]), "r"(a[2]), "r"(a[3]), "r"(b0), "r"(b1));
}
__device__ __forceinline__ void ldmx4(unsigned* r, unsigned addr) {
    asm volatile("ldmatrix.sync.aligned.m8n8.x4.shared.b16 {%0,%1,%2,%3}, [%4];"
        : "=r"(r[0]), "=r"(r[1]), "=r"(r[2]), "=r"(r[3]) : "r"(addr));
}
__device__ __forceinline__ void ldmx4t(unsigned* r, unsigned addr) {
    asm volatile("ldmatrix.sync.aligned.m8n8.x4.trans.shared.b16 {%0,%1,%2,%3}, [%4];"
        : "=r"(r[0]), "=r"(r[1]), "=r"(r[2]), "=r"(r[3]) : "r"(addr));
}
__device__ __forceinline__ unsigned smem_addr(const void* p) {
    return (unsigned)__cvta_generic_to_shared(p);
}

// ---------------- GEMM2 wide: 512 thr, tile 128x192, A loaded once ----------------
__global__ __launch_bounds__(512, 1) void gemm2_wide(
    const float* __restrict__ qry, const float* __restrict__ pos,
    const float* __restrict__ Woff, const float* __restrict__ Wattn,
    const float* __restrict__ boff, const float* __restrict__ battn)
{
    __shared__ __half As[2][128*AST];   // 6144 B per buf
    __shared__ __half Bs[2][192*BST];   // 9216 B per buf
    const int tid = threadIdx.x;
    const int lane = tid & 31, wid = tid >> 5;
    const int mw = (wid & 3) * 32, nw = (wid >> 2) * 48;
    const int g = lane >> 2, t = lane & 3;
    const int m0 = blockIdx.x * 128;

    // A staging: row am (0..127), 1 float4 per array
    const int am = tid >> 2, akq = (tid & 3) * 4;
    const int mga = m0 + am;
    const bool aok = (mga < MROWS);
    // B staging: row br (0..127) always; row 128+br for tid<256
    const int br = tid >> 2, bkq = (tid & 3) * 4;
    const float* wrow0 = Woff + (size_t)br*DIM;
    const bool hasB2 = (tid < 256);
    const float* wrow1 = Wattn + (size_t)br*DIM;   // row 128+br

    const unsigned as_base = smem_addr(&As[0][0]);
    const unsigned bs_base = smem_addr(&Bs[0][0]);
    const int bit3 = (lane >> 3) & 1, bit4 = lane >> 4;
    const unsigned aoffs = (unsigned)(((mw + (lane & 7) + bit3*8) * AST + bit4*8) << 1);
    const unsigned boffs = (unsigned)(((nw + (lane & 7) + bit3*8) * BST + bit4*8) << 1);

    float c_[2][6][4];
    #pragma unroll
    for (int mi = 0; mi < 2; mi++)
        #pragma unroll
        for (int ni = 0; ni < 6; ni++)
            #pragma unroll
            for (int r = 0; r < 4; r++) c_[mi][ni][r] = 0.f;

    float4 pa0, pa1, pb0, pb1;
    auto zero4 = make_float4(0.f, 0.f, 0.f, 0.f);
    #define G2_LOAD(k0) do {                                                        \
        pa0 = zero4; pa1 = zero4;                                                   \
        if (aok) {                                                                  \
            pa0 = *(const float4*)(qry + (size_t)mga*DIM + (k0) + akq);             \
            pa1 = *(const float4*)(pos + (size_t)mga*DIM + (k0) + akq);             \
        }                                                                           \
        pb0 = *(const float4*)(wrow0 + (k0) + bkq);                                 \
        pb1 = hasB2 ? *(const float4*)(wrow1 + (k0) + bkq) : zero4;                 \
    } while (0)

    #define G2_STORE(buf) do {                                                     \
        float4 s = make_float4(pa0.x+pa1.x, pa0.y+pa1.y, pa0.z+pa1.z, pa0.w+pa1.w);\
        *(uint2*)&As[buf][am*AST + akq] = make_uint2(p2(s.x,s.y), p2(s.z,s.w));    \
        *(uint2*)&Bs[buf][br*BST + bkq] = make_uint2(p2(pb0.x,pb0.y), p2(pb0.z,pb0.w));\
        if (hasB2)                                                                  \
            *(uint2*)&Bs[buf][(128+br)*BST + bkq] =                                 \
                make_uint2(p2(pb1.x,pb1.y), p2(pb1.z,pb1.w));                       \
    } while (0)

    G2_LOAD(0);
    G2_STORE(0);
    __syncthreads();

    #pragma unroll 1
    for (int cch = 0; cch < 16; cch++) {
        const int buf = cch & 1;
        if (cch < 15) G2_LOAD((cch + 1) * 16);
        const unsigned aoff = as_base + (unsigned)buf * 6144u;
        const unsigned boff = bs_base + (unsigned)buf * 9216u;
        unsigned a[2][4], b[3][4];
        #pragma unroll
        for (int mi = 0; mi < 2; mi++) ldmx4(a[mi], aoff + aoffs + mi*768u);
        #pragma unroll
        for (int np = 0; np < 3; np++) ldmx4(b[np], boff + boffs + np*768u);
        #pragma unroll
        for (int mi = 0; mi < 2; mi++)
            #pragma unroll
            for (int ni = 0; ni < 6; ni++)
                mma16816(c_[mi][ni], a[mi], b[ni>>1][ni&1], b[ni>>1][(ni&1)+2]);
        if (cch < 15) G2_STORE(buf ^ 1);
        __syncthreads();
    }

    // ---- epilogue ----
    #pragma unroll
    for (int mi = 0; mi < 2; mi++) {
        #pragma unroll
        for (int ni = 0; ni < 6; ni++) {
            const int jc = nw + ni*8 + 2*t;
            const int r0 = mw + mi*16 + g;
            const float* cr = c_[mi][ni];
            float b0, b1;
            if (jc < 128) { b0 = boff[jc]; b1 = boff[jc+1]; }
            else          { b0 = battn[jc-128]; b1 = battn[jc-127]; }
            int mr0 = m0 + r0, mr1 = mr0 + 8;
            if (mr0 < MROWS)
                *(float2*)&d_offattn[(size_t)mr0*OAC + jc] = make_float2(cr[0]+b0, cr[1]+b1);
            if (mr1 < MROWS)
                *(float2*)&d_offattn[(size_t)mr1*OAC + jc] = make_float2(cr[2]+b0, cr[3]+b1);
        }
    }
    #undef G2_LOAD
    #undef G2_STORE
}

// ---------------- fp16 mma.sync GEMM template (MODE 1 value, MODE 3 final) ----------------
template<int MODE>
__global__ __launch_bounds__(256, 2) void gemm_tc(
    const float* __restrict__ A0,
    const float* __restrict__ B0,
    const float* __restrict__ bias0,
    float* __restrict__ C)
{
    __shared__ __half As[2][3072];
    __shared__ __half Bs[2][1536];
    const int tid = threadIdx.x;
    const int lane = tid & 31, wid = tid >> 5;
    const int mw = (wid & 3) * 32, nw = (wid >> 2) * 32;
    const int g = lane >> 2, t = lane & 3;
    const int j0 = blockIdx.x * 64;

    int camI = 0, p0 = 0, m0 = 0;
    if (MODE == 1) { camI = blockIdx.y / 22; p0 = (blockIdx.y % 22) * 128; }
    else m0 = blockIdx.y * 128;

    const float* Aptr = (MODE == 3) ? (const float*)d_S : A0;
    const int bn_ = tid >> 2, bkq = (tid & 3) * 4;
    const int jg = j0 + bn_;
    const float* wrow;
    if (MODE == 3) wrow = (const float*)d_Wc + (size_t)jg*DIM;
    else wrow = B0 + (size_t)jg*DIM;

    const int am = tid >> 1, akq = (tid & 1) * 8;
    const int kk = tid >> 4, pg = tid & 15;
    const int mga = m0 + am;

    const unsigned as_base = smem_addr(&As[0][0]);
    const unsigned bs_base = smem_addr(&Bs[0][0]);
    const int bit3 = (lane >> 3) & 1, bit4 = lane >> 4;
    const unsigned aoffs = (unsigned)(((mw + (lane & 7) + bit3*8) * AST + bit4*8) << 1);
    const unsigned atoffs = (unsigned)((((lane & 7) + bit4*8) * MSTR + mw + bit3*8) << 1);
    const unsigned boffs = (unsigned)(((nw + (lane & 7) + bit3*8) * BST + bit4*8) << 1);

    float c_[2][4][4];
    #pragma unroll
    for (int mi = 0; mi < 2; mi++)
        #pragma unroll
        for (int ni = 0; ni < 4; ni++)
            #pragma unroll
            for (int r = 0; r < 4; r++) c_[mi][ni][r] = 0.f;

    float4 pa0, pa1, pb;
    auto zero4 = make_float4(0.f, 0.f, 0.f, 0.f);
    #define LOAD_CHUNK(k0) do {                                                      \
        if (MODE == 1) {                                                             \
            const float* src = A0 + ((size_t)(camI*DIM + (k0) + kk))*HWF + p0 + pg*8;\
            pa0 = *(const float4*)src; pa1 = *(const float4*)(src + 4);              \
        } else {                                                                     \
            pa0 = zero4; pa1 = zero4;                                                \
            if (mga < QN) {                                                          \
                pa0 = *(const float4*)(Aptr + (size_t)mga*DIM + (k0) + akq);         \
                pa1 = *(const float4*)(Aptr + (size_t)mga*DIM + (k0) + akq + 4);     \
            }                                                                        \
        }                                                                            \
        pb = *(const float4*)(wrow + (k0) + bkq);                                    \
    } while (0)

    #define STORE_CHUNK(buf) do {                                                   \
        uint4 ha = make_uint4(p2(pa0.x,pa0.y), p2(pa0.z,pa0.w),                     \
                              p2(pa1.x,pa1.y), p2(pa1.z,pa1.w));                    \
        if (MODE == 1) *(uint4*)&As[buf][kk*MSTR + pg*8] = ha;                      \
        else           *(uint4*)&As[buf][am*AST + akq]   = ha;                      \
        *(uint2*)&Bs[buf][bn_*BST + bkq] = make_uint2(p2(pb.x,pb.y), p2(pb.z,pb.w));\
    } while (0)

    LOAD_CHUNK(0);
    STORE_CHUNK(0);
    __syncthreads();

    #pragma unroll 1
    for (int cch = 0; cch < 16; cch++) {
        const int buf = cch & 1;
        if (cch < 15) LOAD_CHUNK((cch + 1) * 16);
        const unsigned aoff = as_base + (unsigned)buf * 6144u;
        const unsigned boff = bs_base + (unsigned)buf * 3072u;
        unsigned a[2][4], b[2][4];
        if (MODE == 1) {
            #pragma unroll
            for (int mi = 0; mi < 2; mi++) ldmx4t(a[mi], aoff + atoffs + mi*32u);
        } else {
            #pragma unroll
            for (int mi = 0; mi < 2; mi++) ldmx4(a[mi], aoff + aoffs + mi*768u);
        }
        #pragma unroll
        for (int np = 0; np < 2; np++) ldmx4(b[np], boff + boffs + np*768u);
        #pragma unroll
        for (int mi = 0; mi < 2; mi++) {
            mma16816(c_[mi][0], a[mi], b[0][0], b[0][2]);
            mma16816(c_[mi][1], a[mi], b[0][1], b[0][3]);
            mma16816(c_[mi][2], a[mi], b[1][0], b[1][2]);
            mma16816(c_[mi][3], a[mi], b[1][1], b[1][3]);
        }
        if (cch < 15) STORE_CHUNK(buf ^ 1);
        __syncthreads();
    }

    // ---- epilogue ----
    #pragma unroll
    for (int mi = 0; mi < 2; mi++) {
        #pragma unroll
        for (int ni = 0; ni < 4; ni++) {
            const int jc = j0 + nw + ni*8 + 2*t;
            const int r0 = mw + mi*16 + g;
            const float* cr = c_[mi][ni];
            if (MODE == 1) {
                const int h = jc >> 5, hd = jc & 31;
                float b0 = d_bias2[camI*DIM + jc], b1 = d_bias2[camI*DIM + jc + 1];
                __half* o0 = d_value + ((size_t)(camI*NH + h)*HWF + p0 + r0)*HD + hd;
                __half* o1 = o0 + 8*HD;
                *(__half2*)o0 = __floats2half2_rn(cr[0] + b0, cr[1] + b1);
                *(__half2*)o1 = __floats2half2_rn(cr[2] + b0, cr[3] + b1);
            } else {
                float b0 = bias0[jc] , b1 = bias0[jc+1];
                float e0 = d_bi2[jc], e1 = d_bi2[jc+1];
                int mr0 = m0 + r0, mr1 = mr0 + 8;
                if (mr0 < QN) {
                    float gf = d_gflag[mr0];
                    *(float2*)&C[(size_t)mr0*DIM + jc] =
                        make_float2(cr[0] + b0 + gf*e0, cr[1] + b1 + gf*e1);
                }
                if (mr1 < QN) {
                    float gf = d_gflag[mr1];
                    *(float2*)&C[(size_t)mr1*DIM + jc] =
                        make_float2(cr[2] + b0 + gf*e0, cr[3] + b1 + gf*e1);
                }
            }
        }
    }
    #undef LOAD_CHUNK
    #undef STORE_CHUNK
}

// ---------------- sampling v3: 16B gathers, 2 points/iter ----------------
__global__ __launch_bounds__(256) void sample_kernel(const float* __restrict__ ref,
                                                     const void* __restrict__ mask) {
    const int q = blockIdx.x;
    const int tid = threadIdx.x;
    const int h = tid>>5, l = tid&31;
    const int c8 = l&7;
    const int ox = (l>>3)&1, oy = l>>4;
    const int oct = l&3, corg = (l>>2)&3, psel = l>>4;
    const int oxg = corg&1, oyg = corg>>1;
    const int srcl_base = oyg*16 + oxg*8 + psel;
    __shared__ float s_hit[NCAM];
    __shared__ float s_inv, s_g;
    if (tid < NCAM) {
        const int mode = d_mask_mode;
        size_t base = (size_t)(tid*QN + q)*8;
        int hit = mask_elem(mask, base+0, mode) | mask_elem(mask, base+2, mode) |
                  mask_elem(mask, base+4, mode) | mask_elem(mask, base+6, mode);
        s_hit[tid] = hit ? 1.f : 0.f;
    }
    __syncthreads();
    if (tid == 0) {
        float c = s_hit[0]+s_hit[1]+s_hit[2]+s_hit[3]+s_hit[4]+s_hit[5];
        s_g = (c > 0.f) ? 1.f : 0.f;
        s_inv = 1.f / fmaxf(c, 1.f);
    }
    __syncthreads();
    float acc[8];
    #pragma unroll
    for (int i = 0; i < 8; i++) acc[i] = 0.f;

    for (int camI = 0; camI < NCAM; camI++) {
        if (s_hit[camI] == 0.f) continue;
        const float* row = d_offattn + (size_t)(camI*QN + q)*OAC;
        float logit = row[128 + h*8 + c8];
        float2 of = *(const float2*)(row + h*16 + c8*2);
        const float* rp = ref + ((size_t)(camI*QN + q)*4 + (c8&3))*2;
        float rx = rp[0], ry = rp[1];
        float e = __expf(logit);
        float sm = e;
        sm += __shfl_xor_sync(0xffffffffu, sm, 1, 8);
        sm += __shfl_xor_sync(0xffffffffu, sm, 2, 8);
        sm += __shfl_xor_sync(0xffffffffu, sm, 4, 8);
        float w = __fdividef(e, sm);
        float x = fmaf(rx, (float)WFv, of.x) - 0.5f;
        float y = fmaf(ry, (float)HFv, of.y) - 0.5f;
        float xf = floorf(x), yf = floorf(y);
        float dx = x - xf, dy = y - yf;
        int xi = (int)xf + ox;
        int yi = (int)yf + oy;
        float wx = ox ? dx : (1.f - dx);
        float wy = oy ? dy : (1.f - dy);
        bool valid = (xi >= 0) && (xi < WFv) && (yi >= 0) && (yi < HFv);
        float wc = valid ? (w*wx*wy) : 0.f;
        int pix = min(max(yi,0),HFv-1)*WFv + min(max(xi,0),WFv-1);
        const __half* vh = d_value + (size_t)(camI*NH + h)*HWF*HD + oct*8;
        #pragma unroll
        for (int pp = 0; pp < 4; pp++) {
            int srcl = srcl_base + 2*pp;
            float wcp = __shfl_sync(0xffffffffu, wc,  srcl);
            int  pixp = __shfl_sync(0xffffffffu, pix, srcl);
            uint4 raw = *(const uint4*)(vh + (size_t)pixp*HD);
            float2 f0 = __half22float2(*(__half2*)&raw.x);
            float2 f1 = __half22float2(*(__half2*)&raw.y);
            float2 f2 = __half22float2(*(__half2*)&raw.z);
            float2 f3 = __half22float2(*(__half2*)&raw.w);
            acc[0] = fmaf(wcp, f0.x, acc[0]); acc[1] = fmaf(wcp, f0.y, acc[1]);
            acc[2] = fmaf(wcp, f1.x, acc[2]); acc[3] = fmaf(wcp, f1.y, acc[3]);
            acc[4] = fmaf(wcp, f2.x, acc[4]); acc[5] = fmaf(wcp, f2.y, acc[5]);
            acc[6] = fmaf(wcp, f3.x, acc[6]); acc[7] = fmaf(wcp, f3.y, acc[7]);
        }
    }
    #pragma unroll
    for (int i = 0; i < 8; i++) {
        acc[i] += __shfl_xor_sync(0xffffffffu, acc[i], 4);
        acc[i] += __shfl_xor_sync(0xffffffffu, acc[i], 8);
        acc[i] += __shfl_xor_sync(0xffffffffu, acc[i], 16);
    }
    if (l < 4) {
        float inv = s_inv;
        float* o = d_S + (size_t)q*DIM + h*HD + l*8;
        *(float4*)o       = make_float4(acc[0]*inv, acc[1]*inv, acc[2]*inv, acc[3]*inv);
        *(float4*)(o + 4) = make_float4(acc[4]*inv, acc[5]*inv, acc[6]*inv, acc[7]*inv);
    }
    if (tid == 0) d_gflag[q] = s_g;
}

// ---------------- launch ----------------
extern "C" void kernel_launch(void* const* d_in, const int* in_sizes, int n_in,
                              void* d_out, int out_size) {
    const float* queries = (const float*)d_in[0];
    const float* pos     = (const float*)d_in[1];
    const float* lvl     = (const float*)d_in[2];
    const float* camemb  = (const float*)d_in[3];
    const float* feat    = (const float*)d_in[4];
    const float* ref     = (const float*)d_in[5];
    const void*  mask    = (const void*)d_in[6];
    const float* W_value = (const float*)d_in[7];
    const float* b_value = (const float*)d_in[8];
    const float* W_off   = (const float*)d_in[9];
    const float* b_off   = (const float*)d_in[10];
    const float* W_attn  = (const float*)d_in[11];
    const float* b_attn  = (const float*)d_in[12];
    const float* W_inner = (const float*)d_in[13];
    const float* b_inner = (const float*)d_in[14];
    const float* W_out   = (const float*)d_in[15];
    const float* b_out   = (const float*)d_in[16];
    float* out = (float*)d_out;

    prep_a<<<NCAM + 1, DIM>>>(lvl, camemb, W_value, b_value, (const unsigned int*)mask);
    prep_b<<<DIM + 1, DIM>>>(W_out, W_inner, b_inner);
    gemm_tc<1><<<dim3(4, 132), 256>>>(feat, W_value, nullptr, nullptr);
    gemm2_wide<<<469, 512>>>(queries, pos, W_off, W_attn, b_off, b_attn);
    sample_kernel<<<QN, 256>>>(ref, mask);
    gemm_tc<3><<<dim3(4, 79), 256>>>(nullptr, nullptr, b_out, out);
    (void)in_sizes; (void)n_in; (void)out_size;
}

// round 12
// speedup vs baseline: 1.5055x; 1.0055x over previous
#include <cuda_runtime.h>
#include <cuda_fp16.h>
#include <cstdint>

#define QN   10000
#define NCAM 6
#define DIM  256
#define HWF  2816     // 32*88
#define NH   8
#define HD   32
#define HFv  32
#define WFv  88
#define MROWS (NCAM*QN)   // 60000
#define OAC  192          // 128 offsets + 64 attn logits

// ---------------- scratch ----------------
__device__ __half d_value[NCAM*NH*HWF*HD];  // (cam, head, hw, hd) fp16
__device__ float d_offattn[(size_t)MROWS*OAC];
__device__ float d_S[(size_t)QN*DIM];
__device__ float d_gflag[QN];
__device__ float d_bias2[NCAM*DIM];
__device__ float d_Wc[DIM*DIM];             // W_out @ W_inner
__device__ float d_bi2[DIM];                // W_out @ b_inner
__device__ int   d_mask_mode;               // 0=u8, 1=i32, 2=f32

__device__ __forceinline__ int mask_elem(const void* mask, size_t idx, int mode) {
    if (mode == 0) return ((const unsigned char*)mask)[idx] != 0;
    if (mode == 1) return ((const int*)mask)[idx] != 0;
    return ((const float*)mask)[idx] != 0.f;
}

// ---------------- prep A: bias2 (blocks 0..5) + mask detect (block 6) ----------------
__global__ void prep_a(const float* __restrict__ lvl, const float* __restrict__ camemb,
                       const float* __restrict__ Wv, const float* __restrict__ bv,
                       const unsigned int* __restrict__ mk) {
    int c = blockIdx.x, j = threadIdx.x;
    if (c == NCAM) {
        if (j < 32) {
            bool f = false, multi = false;
            for (int i = j; i < 256; i += 32) {
                unsigned int w = mk[i];
                f |= (w == 0x3F800000u);
                multi |= (w != 0x3F800000u && w > 1u);
            }
            unsigned bf = __ballot_sync(0xffffffffu, f), bm = __ballot_sync(0xffffffffu, multi);
            if (j == 0) d_mask_mode = bf ? 2 : (bm ? 0 : 1);
        }
        return;
    }
    __shared__ float e[DIM];
    e[j] = lvl[j] + camemb[c*DIM + j];
    __syncthreads();
    const float4* w4 = (const float4*)(Wv + (size_t)j*DIM);
    const float4* e4 = (const float4*)e;
    float s = bv[j];
    #pragma unroll 8
    for (int k = 0; k < DIM/4; k++) {
        float4 w = w4[k]; float4 ev = e4[k];
        s += w.x*ev.x + w.y*ev.y + w.z*ev.z + w.w*ev.w;
    }
    d_bias2[c*DIM + j] = s;
}

// ---------------- prep B: Wc (blocks 0..255) + bi2 (block 256) ----------------
__global__ void prep_b(const float* __restrict__ Wo, const float* __restrict__ Wi,
                       const float* __restrict__ bi) {
    int i = blockIdx.x, j = threadIdx.x;
    if (i == DIM) {
        int w = j >> 5, l = j & 31;
        for (int ii = w; ii < DIM; ii += 8) {
            float s = 0.f;
            #pragma unroll
            for (int t = 0; t < 8; t++) {
                int k = l + 32*t;
                s += Wo[(size_t)ii*DIM + k] * bi[k];
            }
            #pragma unroll
            for (int o = 16; o; o >>= 1) s += __shfl_xor_sync(0xffffffffu, s, o);
            if (l == 0) d_bi2[ii] = s;
        }
        return;
    }
    __shared__ float wo[DIM];
    wo[j] = Wo[(size_t)i*DIM + j];
    __syncthreads();
    float s = 0.f;
    #pragma unroll 8
    for (int k = 0; k < DIM; k++) s += wo[k] * Wi[(size_t)k*DIM + j];
    d_Wc[(size_t)i*DIM + j] = s;
}

// ---------------- fp16 mma common ----------------
#define AST 24
#define MSTR 136
#define BST 24

__device__ __forceinline__ unsigned p2(float x, float y) {
    __half2 h = __floats2half2_rn(x, y);
    return *(unsigned*)&h;
}
__device__ __forceinline__ void mma16816(float* c, const unsigned* a, unsigned b0, unsigned b1) {
    asm volatile("mma.sync.aligned.m16n8k16.row.col.f32.f16.f16.f32 "
        "{%0,%1,%2,%3}, {%4,%5,%6,%7}, {%8,%9}, {%0,%1,%2,%3};"
        : "+f"(c[0]), "+f"(c[1]), "+f"(c[2]), "+f"(c[3])
        : "r"(a[0]), "r"(a[1]), "r"(a[2]), "r"(a[3]), "r"(b0), "r"(b1));
}
__device__ __forceinline__ void ldmx4(unsigned* r, unsigned addr) {
    asm volatile("ldmatrix.sync.aligned.m8n8.x4.shared.b16 {%0,%1,%2,%3}, [%4];"
        : "=r"(r[0]), "=r"(r[1]), "=r"(r[2]), "=r"(r[3]) : "r"(addr));
}
__device__ __forceinline__ void ldmx4t(unsigned* r, unsigned addr) {
    asm volatile("ldmatrix.sync.aligned.m8n8.x4.trans.shared.b16 {%0,%1,%2,%3}, [%4];"
        : "=r"(r[0]), "=r"(r[1]), "=r"(r[2]), "=r"(r[3]) : "r"(addr));
}
__device__ __forceinline__ unsigned smem_addr(const void* p) {
    return (unsigned)__cvta_generic_to_shared(p);
}

// ---------------- GEMM2: 256 thr, tile 64x192, 2 CTAs/SM ----------------
__global__ __launch_bounds__(256, 2) void gemm2_wide(
    const float* __restrict__ qry, const float* __restrict__ pos,
    const float* __restrict__ Woff, const float* __restrict__ Wattn,
    const float* __restrict__ boff, const float* __restrict__ battn)
{
    __shared__ __half As[2][64*AST];    // 3072 B per buf
    __shared__ __half Bs[2][192*BST];   // 9216 B per buf
    const int tid = threadIdx.x;
    const int lane = tid & 31, wid = tid >> 5;
    const int mw = (wid & 1) * 32, nw = (wid >> 1) * 48;
    const int g = lane >> 2, t = lane & 3;
    const int m0 = blockIdx.x * 64;

    // A staging: row am (0..63), 1 float4 pair per thread
    const int am = tid >> 2, akq = (tid & 3) * 4;
    const int mga = m0 + am;
    const bool aok = (mga < MROWS);
    // B staging: rows br, br+64 (Woff), 128+br (Wattn)
    const int br = tid >> 2, bkq = (tid & 3) * 4;
    const float* wrow0 = Woff + (size_t)br*DIM;
    const float* wrow1 = Woff + (size_t)(br+64)*DIM;
    const float* wrow2 = Wattn + (size_t)br*DIM;

    const unsigned as_base = smem_addr(&As[0][0]);
    const unsigned bs_base = smem_addr(&Bs[0][0]);
    const int bit3 = (lane >> 3) & 1, bit4 = lane >> 4;
    const unsigned aoffs = (unsigned)(((mw + (lane & 7) + bit3*8) * AST + bit4*8) << 1);
    const unsigned boffs = (unsigned)(((nw + (lane & 7) + bit3*8) * BST + bit4*8) << 1);

    float c_[2][6][4];
    #pragma unroll
    for (int mi = 0; mi < 2; mi++)
        #pragma unroll
        for (int ni = 0; ni < 6; ni++)
            #pragma unroll
            for (int r = 0; r < 4; r++) c_[mi][ni][r] = 0.f;

    float4 pa0, pa1, pb0, pb1, pb2;
    auto zero4 = make_float4(0.f, 0.f, 0.f, 0.f);
    #define G2_LOAD(k0) do {                                                        \
        pa0 = zero4; pa1 = zero4;                                                   \
        if (aok) {                                                                  \
            pa0 = *(const float4*)(qry + (size_t)mga*DIM + (k0) + akq);             \
            pa1 = *(const float4*)(pos + (size_t)mga*DIM + (k0) + akq);             \
        }                                                                           \
        pb0 = *(const float4*)(wrow0 + (k0) + bkq);                                 \
        pb1 = *(const float4*)(wrow1 + (k0) + bkq);                                 \
        pb2 = *(const float4*)(wrow2 + (k0) + bkq);                                 \
    } while (0)

    #define G2_STORE(buf) do {                                                     \
        float4 s = make_float4(pa0.x+pa1.x, pa0.y+pa1.y, pa0.z+pa1.z, pa0.w+pa1.w);\
        *(uint2*)&As[buf][am*AST + akq] = make_uint2(p2(s.x,s.y), p2(s.z,s.w));    \
        *(uint2*)&Bs[buf][br*BST + bkq] = make_uint2(p2(pb0.x,pb0.y), p2(pb0.z,pb0.w));\
        *(uint2*)&Bs[buf][(64+br)*BST + bkq] = make_uint2(p2(pb1.x,pb1.y), p2(pb1.z,pb1.w));\
        *(uint2*)&Bs[buf][(128+br)*BST + bkq] = make_uint2(p2(pb2.x,pb2.y), p2(pb2.z,pb2.w));\
    } while (0)

    G2_LOAD(0);
    G2_STORE(0);
    __syncthreads();

    #pragma unroll 1
    for (int cch = 0; cch < 16; cch++) {
        const int buf = cch & 1;
        if (cch < 15) G2_LOAD((cch + 1) * 16);
        const unsigned aoff = as_base + (unsigned)buf * 3072u;
        const unsigned boff = bs_base + (unsigned)buf * 9216u;
        unsigned a[2][4], b[3][4];
        #pragma unroll
        for (int mi = 0; mi < 2; mi++) ldmx4(a[mi], aoff + aoffs + mi*768u);
        #pragma unroll
        for (int np = 0; np < 3; np++) ldmx4(b[np], boff + boffs + np*768u);
        #pragma unroll
        for (int mi = 0; mi < 2; mi++)
            #pragma unroll
            for (int ni = 0; ni < 6; ni++)
                mma16816(c_[mi][ni], a[mi], b[ni>>1][ni&1], b[ni>>1][(ni&1)+2]);
        if (cch < 15) G2_STORE(buf ^ 1);
        __syncthreads();
    }

    // ---- epilogue ----
    #pragma unroll
    for (int mi = 0; mi < 2; mi++) {
        #pragma unroll
        for (int ni = 0; ni < 6; ni++) {
            const int jc = nw + ni*8 + 2*t;
            const int r0 = mw + mi*16 + g;
            const float* cr = c_[mi][ni];
            float b0, b1;
            if (jc < 128) { b0 = boff[jc]; b1 = boff[jc+1]; }
            else          { b0 = battn[jc-128]; b1 = battn[jc-127]; }
            int mr0 = m0 + r0, mr1 = mr0 + 8;
            if (mr0 < MROWS)
                *(float2*)&d_offattn[(size_t)mr0*OAC + jc] = make_float2(cr[0]+b0, cr[1]+b1);
            if (mr1 < MROWS)
                *(float2*)&d_offattn[(size_t)mr1*OAC + jc] = make_float2(cr[2]+b0, cr[3]+b1);
        }
    }
    #undef G2_LOAD
    #undef G2_STORE
}

// ---------------- fp16 mma.sync GEMM template (MODE 1 value, MODE 3 final) ----------------
template<int MODE>
__global__ __launch_bounds__(256, 2) void gemm_tc(
    const float* __restrict__ A0,
    const float* __restrict__ B0,
    const float* __restrict__ bias0,
    float* __restrict__ C)
{
    __shared__ __half As[2][3072];
    __shared__ __half Bs[2][1536];
    const int tid = threadIdx.x;
    const int lane = tid & 31, wid = tid >> 5;
    const int mw = (wid & 3) * 32, nw = (wid >> 2) * 32;
    const int g = lane >> 2, t = lane & 3;
    const int j0 = blockIdx.x * 64;

    int camI = 0, p0 = 0, m0 = 0;
    if (MODE == 1) { camI = blockIdx.y / 22; p0 = (blockIdx.y % 22) * 128; }
    else m0 = blockIdx.y * 128;

    const float* Aptr = (MODE == 3) ? (const float*)d_S : A0;
    const int bn_ = tid >> 2, bkq = (tid & 3) * 4;
    const int jg = j0 + bn_;
    const float* wrow;
    if (MODE == 3) wrow = (const float*)d_Wc + (size_t)jg*DIM;
    else wrow = B0 + (size_t)jg*DIM;

    const int am = tid >> 1, akq = (tid & 1) * 8;
    const int kk = tid >> 4, pg = tid & 15;
    const int mga = m0 + am;

    const unsigned as_base = smem_addr(&As[0][0]);
    const unsigned bs_base = smem_addr(&Bs[0][0]);
    const int bit3 = (lane >> 3) & 1, bit4 = lane >> 4;
    const unsigned aoffs = (unsigned)(((mw + (lane & 7) + bit3*8) * AST + bit4*8) << 1);
    const unsigned atoffs = (unsigned)((((lane & 7) + bit4*8) * MSTR + mw + bit3*8) << 1);
    const unsigned boffs = (unsigned)(((nw + (lane & 7) + bit3*8) * BST + bit4*8) << 1);

    float c_[2][4][4];
    #pragma unroll
    for (int mi = 0; mi < 2; mi++)
        #pragma unroll
        for (int ni = 0; ni < 4; ni++)
            #pragma unroll
            for (int r = 0; r < 4; r++) c_[mi][ni][r] = 0.f;

    float4 pa0, pa1, pb;
    auto zero4 = make_float4(0.f, 0.f, 0.f, 0.f);
    #define LOAD_CHUNK(k0) do {                                                      \
        if (MODE == 1) {                                                             \
            const float* src = A0 + ((size_t)(camI*DIM + (k0) + kk))*HWF + p0 + pg*8;\
            pa0 = *(const float4*)src; pa1 = *(const float4*)(src + 4);              \
        } else {                                                                     \
            pa0 = zero4; pa1 = zero4;                                                \
            if (mga < QN) {                                                          \
                pa0 = *(const float4*)(Aptr + (size_t)mga*DIM + (k0) + akq);         \
                pa1 = *(const float4*)(Aptr + (size_t)mga*DIM + (k0) + akq + 4);     \
            }                                                                        \
        }                                                                            \
        pb = *(const float4*)(wrow + (k0) + bkq);                                    \
    } while (0)

    #define STORE_CHUNK(buf) do {                                                   \
        uint4 ha = make_uint4(p2(pa0.x,pa0.y), p2(pa0.z,pa0.w),                     \
                              p2(pa1.x,pa1.y), p2(pa1.z,pa1.w));                    \
        if (MODE == 1) *(uint4*)&As[buf][kk*MSTR + pg*8] = ha;                      \
        else           *(uint4*)&As[buf][am*AST + akq]   = ha;                      \
        *(uint2*)&Bs[buf][bn_*BST + bkq] = make_uint2(p2(pb.x,pb.y), p2(pb.z,pb.w));\
    } while (0)

    LOAD_CHUNK(0);
    STORE_CHUNK(0);
    __syncthreads();

    #pragma unroll 1
    for (int cch = 0; cch < 16; cch++) {
        const int buf = cch & 1;
        if (cch < 15) LOAD_CHUNK((cch + 1) * 16);
        const unsigned aoff = as_base + (unsigned)buf * 6144u;
        const unsigned boff = bs_base + (unsigned)buf * 3072u;
        unsigned a[2][4], b[2][4];
        if (MODE == 1) {
            #pragma unroll
            for (int mi = 0; mi < 2; mi++) ldmx4t(a[mi], aoff + atoffs + mi*32u);
        } else {
            #pragma unroll
            for (int mi = 0; mi < 2; mi++) ldmx4(a[mi], aoff + aoffs + mi*768u);
        }
        #pragma unroll
        for (int np = 0; np < 2; np++) ldmx4(b[np], boff + boffs + np*768u);
        #pragma unroll
        for (int mi = 0; mi < 2; mi++) {
            mma16816(c_[mi][0], a[mi], b[0][0], b[0][2]);
            mma16816(c_[mi][1], a[mi], b[0][1], b[0][3]);
            mma16816(c_[mi][2], a[mi], b[1][0], b[1][2]);
            mma16816(c_[mi][3], a[mi], b[1][1], b[1][3]);
        }
        if (cch < 15) STORE_CHUNK(buf ^ 1);
        __syncthreads();
    }

    // ---- epilogue ----
    #pragma unroll
    for (int mi = 0; mi < 2; mi++) {
        #pragma unroll
        for (int ni = 0; ni < 4; ni++) {
            const int jc = j0 + nw + ni*8 + 2*t;
            const int r0 = mw + mi*16 + g;
            const float* cr = c_[mi][ni];
            if (MODE == 1) {
                const int h = jc >> 5, hd = jc & 31;
                float b0 = d_bias2[camI*DIM + jc], b1 = d_bias2[camI*DIM + jc + 1];
                __half* o0 = d_value + ((size_t)(camI*NH + h)*HWF + p0 + r0)*HD + hd;
                __half* o1 = o0 + 8*HD;
                *(__half2*)o0 = __floats2half2_rn(cr[0] + b0, cr[1] + b1);
                *(__half2*)o1 = __floats2half2_rn(cr[2] + b0, cr[3] + b1);
            } else {
                float b0 = bias0[jc] , b1 = bias0[jc+1];
                float e0 = d_bi2[jc], e1 = d_bi2[jc+1];
                int mr0 = m0 + r0, mr1 = mr0 + 8;
                if (mr0 < QN) {
                    float gf = d_gflag[mr0];
                    *(float2*)&C[(size_t)mr0*DIM + jc] =
                        make_float2(cr[0] + b0 + gf*e0, cr[1] + b1 + gf*e1);
                }
                if (mr1 < QN) {
                    float gf = d_gflag[mr1];
                    *(float2*)&C[(size_t)mr1*DIM + jc] =
                        make_float2(cr[2] + b0 + gf*e0, cr[3] + b1 + gf*e1);
                }
            }
        }
    }
    #undef LOAD_CHUNK
    #undef STORE_CHUNK
}

// ---------------- sampling v3: 16B gathers, 2 points/iter ----------------
__global__ __launch_bounds__(256) void sample_kernel(const float* __restrict__ ref,
                                                     const void* __restrict__ mask) {
    const int q = blockIdx.x;
    const int tid = threadIdx.x;
    const int h = tid>>5, l = tid&31;
    const int c8 = l&7;
    const int ox = (l>>3)&1, oy = l>>4;
    const int oct = l&3, corg = (l>>2)&3, psel = l>>4;
    const int oxg = corg&1, oyg = corg>>1;
    const int srcl_base = oyg*16 + oxg*8 + psel;
    __shared__ float s_hit[NCAM];
    __shared__ float s_inv, s_g;
    if (tid < NCAM) {
        const int mode = d_mask_mode;
        size_t base = (size_t)(tid*QN + q)*8;
        int hit = mask_elem(mask, base+0, mode) | mask_elem(mask, base+2, mode) |
                  mask_elem(mask, base+4, mode) | mask_elem(mask, base+6, mode);
        s_hit[tid] = hit ? 1.f : 0.f;
    }
    __syncthreads();
    if (tid == 0) {
        float c = s_hit[0]+s_hit[1]+s_hit[2]+s_hit[3]+s_hit[4]+s_hit[5];
        s_g = (c > 0.f) ? 1.f : 0.f;
        s_inv = 1.f / fmaxf(c, 1.f);
    }
    __syncthreads();
    float acc[8];
    #pragma unroll
    for (int i = 0; i < 8; i++) acc[i] = 0.f;

    for (int camI = 0; camI < NCAM; camI++) {
        if (s_hit[camI] == 0.f) continue;
        const float* row = d_offattn + (size_t)(camI*QN + q)*OAC;
        float logit = row[128 + h*8 + c8];
        float2 of = *(const float2*)(row + h*16 + c8*2);
        const float* rp = ref + ((size_t)(camI*QN + q)*4 + (c8&3))*2;
        float rx = rp[0], ry = rp[1];
        float e = __expf(logit);
        float sm = e;
        sm += __shfl_xor_sync(0xffffffffu, sm, 1, 8);
        sm += __shfl_xor_sync(0xffffffffu, sm, 2, 8);
        sm += __shfl_xor_sync(0xffffffffu, sm, 4, 8);
        float w = __fdividef(e, sm);
        float x = fmaf(rx, (float)WFv, of.x) - 0.5f;
        float y = fmaf(ry, (float)HFv, of.y) - 0.5f;
        float xf = floorf(x), yf = floorf(y);
        float dx = x - xf, dy = y - yf;
        int xi = (int)xf + ox;
        int yi = (int)yf + oy;
        float wx = ox ? dx : (1.f - dx);
        float wy = oy ? dy : (1.f - dy);
        bool valid = (xi >= 0) && (xi < WFv) && (yi >= 0) && (yi < HFv);
        float wc = valid ? (w*wx*wy) : 0.f;
        int pix = min(max(yi,0),HFv-1)*WFv + min(max(xi,0),WFv-1);
        const __half* vh = d_value + (size_t)(camI*NH + h)*HWF*HD + oct*8;
        #pragma unroll
        for (int pp = 0; pp < 4; pp++) {
            int srcl = srcl_base + 2*pp;
            float wcp = __shfl_sync(0xffffffffu, wc,  srcl);
            int  pixp = __shfl_sync(0xffffffffu, pix, srcl);
            uint4 raw = *(const uint4*)(vh + (size_t)pixp*HD);
            float2 f0 = __half22float2(*(__half2*)&raw.x);
            float2 f1 = __half22float2(*(__half2*)&raw.y);
            float2 f2 = __half22float2(*(__half2*)&raw.z);
            float2 f3 = __half22float2(*(__half2*)&raw.w);
            acc[0] = fmaf(wcp, f0.x, acc[0]); acc[1] = fmaf(wcp, f0.y, acc[1]);
            acc[2] = fmaf(wcp, f1.x, acc[2]); acc[3] = fmaf(wcp, f1.y, acc[3]);
            acc[4] = fmaf(wcp, f2.x, acc[4]); acc[5] = fmaf(wcp, f2.y, acc[5]);
            acc[6] = fmaf(wcp, f3.x, acc[6]); acc[7] = fmaf(wcp, f3.y, acc[7]);
        }
    }
    #pragma unroll
    for (int i = 0; i < 8; i++) {
        acc[i] += __shfl_xor_sync(0xffffffffu, acc[i], 4);
        acc[i] += __shfl_xor_sync(0xffffffffu, acc[i], 8);
        acc[i] += __shfl_xor_sync(0xffffffffu, acc[i], 16);
    }
    if (l < 4) {
        float inv = s_inv;
        float* o = d_S + (size_t)q*DIM + h*HD + l*8;
        *(float4*)o       = make_float4(acc[0]*inv, acc[1]*inv, acc[2]*inv, acc[3]*inv);
        *(float4*)(o + 4) = make_float4(acc[4]*inv, acc[5]*inv, acc[6]*inv, acc[7]*inv);
    }
    if (tid == 0) d_gflag[q] = s_g;
}

// ---------------- launch ----------------
extern "C" void kernel_launch(void* const* d_in, const int* in_sizes, int n_in,
                              void* d_out, int out_size) {
    const float* queries = (const float*)d_in[0];
    const float* pos     = (const float*)d_in[1];
    const float* lvl     = (const float*)d_in[2];
    const float* camemb  = (const float*)d_in[3];
    const float* feat    = (const float*)d_in[4];
    const float* ref     = (const float*)d_in[5];
    const void*  mask    = (const void*)d_in[6];
    const float* W_value = (const float*)d_in[7];
    const float* b_value = (const float*)d_in[8];
    const float* W_off   = (const float*)d_in[9];
    const float* b_off   = (const float*)d_in[10];
    const float* W_attn  = (const float*)d_in[11];
    const float* b_attn  = (const float*)d_in[12];
    const float* W_inner = (const float*)d_in[13];
    const float* b_inner = (const float*)d_in[14];
    const float* W_out   = (const float*)d_in[15];
    const float* b_out   = (const float*)d_in[16];
    float* out = (float*)d_out;

    prep_a<<<NCAM + 1, DIM>>>(lvl, camemb, W_value, b_value, (const unsigned int*)mask);
    prep_b<<<DIM + 1, DIM>>>(W_out, W_inner, b_inner);
    gemm_tc<1><<<dim3(4, 132), 256>>>(feat, W_value, nullptr, nullptr);
    gemm2_wide<<<938, 256>>>(queries, pos, W_off, W_attn, b_off, b_attn);
    sample_kernel<<<QN, 256>>>(ref, mask);
    gemm_tc<3><<<dim3(4, 79), 256>>>(nullptr, nullptr, b_out, out);
    (void)in_sizes; (void)n_in; (void)out_size;
}

// round 17
// speedup vs baseline: 1.5476x; 1.0280x over previous
#include <cuda_runtime.h>
#include <cuda_fp16.h>
#include <cstdint>

#define QN   10000
#define NCAM 6
#define DIM  256
#define HWF  2816     // 32*88
#define NH   8
#define HD   32
#define HFv  32
#define WFv  88
#define MROWS (NCAM*QN)   // 60000
#define OAC  192          // 128 offsets + 64 attn logits

// ---------------- scratch ----------------
__device__ __half d_value[NCAM*NH*HWF*HD];  // (cam, head, hw, hd) fp16
__device__ float d_offattn[(size_t)MROWS*OAC];
__device__ float d_S[(size_t)QN*DIM];
__device__ float d_gflag[QN];
__device__ float d_bias2[NCAM*DIM];
__device__ float d_Wc[DIM*DIM];             // W_out @ W_inner
__device__ float d_bi2[DIM];                // W_out @ b_inner
__device__ int   d_mask_mode;               // 0=u8, 1=i32, 2=f32

__device__ __forceinline__ int mask_elem(const void* mask, size_t idx, int mode) {
    if (mode == 0) return ((const unsigned char*)mask)[idx] != 0;
    if (mode == 1) return ((const int*)mask)[idx] != 0;
    return ((const float*)mask)[idx] != 0.f;
}

// ---------------- prep A: bias2 (blocks 0..5) + mask detect (block 6) ----------------
__global__ void prep_a(const float* __restrict__ lvl, const float* __restrict__ camemb,
                       const float* __restrict__ Wv, const float* __restrict__ bv,
                       const unsigned int* __restrict__ mk) {
    int c = blockIdx.x, j = threadIdx.x;
    if (c == NCAM) {
        if (j < 32) {
            bool f = false, multi = false;
            for (int i = j; i < 256; i += 32) {
                unsigned int w = mk[i];
                f |= (w == 0x3F800000u);
                multi |= (w != 0x3F800000u && w > 1u);
            }
            unsigned bf = __ballot_sync(0xffffffffu, f), bm = __ballot_sync(0xffffffffu, multi);
            if (j == 0) d_mask_mode = bf ? 2 : (bm ? 0 : 1);
        }
        return;
    }
    __shared__ float e[DIM];
    e[j] = lvl[j] + camemb[c*DIM + j];
    __syncthreads();
    const float4* w4 = (const float4*)(Wv + (size_t)j*DIM);
    const float4* e4 = (const float4*)e;
    float s = bv[j];
    #pragma unroll 8
    for (int k = 0; k < DIM/4; k++) {
        float4 w = w4[k]; float4 ev = e4[k];
        s += w.x*ev.x + w.y*ev.y + w.z*ev.z + w.w*ev.w;
    }
    d_bias2[c*DIM + j] = s;
}

// ---------------- prep B: Wc (blocks 0..255) + bi2 (block 256) ----------------
__global__ void prep_b(const float* __restrict__ Wo, const float* __restrict__ Wi,
                       const float* __restrict__ bi) {
    int i = blockIdx.x, j = threadIdx.x;
    if (i == DIM) {
        int w = j >> 5, l = j & 31;
        for (int ii = w; ii < DIM; ii += 8) {
            float s = 0.f;
            #pragma unroll
            for (int t = 0; t < 8; t++) {
                int k = l + 32*t;
                s += Wo[(size_t)ii*DIM + k] * bi[k];
            }
            #pragma unroll
            for (int o = 16; o; o >>= 1) s += __shfl_xor_sync(0xffffffffu, s, o);
            if (l == 0) d_bi2[ii] = s;
        }
        return;
    }
    __shared__ float wo[DIM];
    wo[j] = Wo[(size_t)i*DIM + j];
    __syncthreads();
    float s = 0.f;
    #pragma unroll 8
    for (int k = 0; k < DIM; k++) s += wo[k] * Wi[(size_t)k*DIM + j];
    d_Wc[(size_t)i*DIM + j] = s;
}

// ---------------- fp16 mma common ----------------
#define AST 24
#define MSTR 136
#define BST 24

__device__ __forceinline__ unsigned p2(float x, float y) {
    __half2 h = __floats2half2_rn(x, y);
    return *(unsigned*)&h;
}
__device__ __forceinline__ void mma16816(float* c, const unsigned* a, unsigned b0, unsigned b1) {
    asm volatile("mma.sync.aligned.m16n8k16.row.col.f32.f16.f16.f32 "
        "{%0,%1,%2,%3}, {%4,%5,%6,%7}, {%8,%9}, {%0,%1,%2,%3};"
        : "+f"(c[0]), "+f"(c[1]), "+f"(c[2]), "+f"(c[3])
        : "r"(a[0]), "r"(a[1]), "r"(a[2]), "r"(a[3]), "r"(b0), "r"(b1));
}
__device__ __forceinline__ void ldmx4(unsigned* r, unsigned addr) {
    asm volatile("ldmatrix.sync.aligned.m8n8.x4.shared.b16 {%0,%1,%2,%3}, [%4];"
        : "=r"(r[0]), "=r"(r[1]), "=r"(r[2]), "=r"(r[3]) : "r"(addr));
}
__device__ __forceinline__ void ldmx4t(unsigned* r, unsigned addr) {
    asm volatile("ldmatrix.sync.aligned.m8n8.x4.trans.shared.b16 {%0,%1,%2,%3}, [%4];"
        : "=r"(r[0]), "=r"(r[1]), "=r"(r[2]), "=r"(r[3]) : "r"(addr));
}
__device__ __forceinline__ unsigned smem_addr(const void* p) {
    return (unsigned)__cvta_generic_to_shared(p);
}

// ---------------- FAT kernel: GEMM2 (blocks 0..937) + GEMM1 (blocks 938..1465) ----------------
#define G2_BLOCKS 938
__global__ __launch_bounds__(256, 2) void fat_gemm(
    const float* __restrict__ feat, const float* __restrict__ Wv,
    const float* __restrict__ qry, const float* __restrict__ pos,
    const float* __restrict__ Woff, const float* __restrict__ Wattn,
    const float* __restrict__ boff2, const float* __restrict__ battn)
{
    __shared__ char smraw[24576];
    const int tid = threadIdx.x;
    const int lane = tid & 31, wid = tid >> 5;
    const int g = lane >> 2, t = lane & 3;
    const int bit3 = (lane >> 3) & 1, bit4 = lane >> 4;

    if (blockIdx.x < G2_BLOCKS) {
        // ================= GEMM2 body: tile 64x192 =================
        __half* As = (__half*)smraw;              // 2 bufs x 1536 halves (3072B each)
        __half* Bs = (__half*)(smraw + 6144);     // 2 bufs x 4608 halves (9216B each)
        const int mw = (wid & 1) * 32, nw = (wid >> 1) * 48;
        const int m0 = blockIdx.x * 64;

        const int am = tid >> 2, akq = (tid & 3) * 4;
        const int mga = m0 + am;
        const bool aok = (mga < MROWS);
        const int br = tid >> 2, bkq = (tid & 3) * 4;
        const float* wrow0 = Woff + (size_t)br*DIM;
        const float* wrow1 = Woff + (size_t)(br+64)*DIM;
        const float* wrow2 = Wattn + (size_t)br*DIM;

        const unsigned as_base = smem_addr(As);
        const unsigned bs_base = smem_addr(Bs);
        const unsigned aoffs = (unsigned)(((mw + (lane & 7) + bit3*8) * AST + bit4*8) << 1);
        const unsigned boffs = (unsigned)(((nw + (lane & 7) + bit3*8) * BST + bit4*8) << 1);

        float c_[2][6][4];
        #pragma unroll
        for (int mi = 0; mi < 2; mi++)
            #pragma unroll
            for (int ni = 0; ni < 6; ni++)
                #pragma unroll
                for (int r = 0; r < 4; r++) c_[mi][ni][r] = 0.f;

        float4 pa0, pa1, pb0, pb1, pb2;
        auto zero4 = make_float4(0.f, 0.f, 0.f, 0.f);
        #define G2_LOAD(k0) do {                                                        \
            pa0 = zero4; pa1 = zero4;                                                   \
            if (aok) {                                                                  \
                pa0 = *(const float4*)(qry + (size_t)mga*DIM + (k0) + akq);             \
                pa1 = *(const float4*)(pos + (size_t)mga*DIM + (k0) + akq);             \
            }                                                                           \
            pb0 = *(const float4*)(wrow0 + (k0) + bkq);                                 \
            pb1 = *(const float4*)(wrow1 + (k0) + bkq);                                 \
            pb2 = *(const float4*)(wrow2 + (k0) + bkq);                                 \
        } while (0)
        #define G2_STORE(buf) do {                                                     \
            float4 s = make_float4(pa0.x+pa1.x, pa0.y+pa1.y, pa0.z+pa1.z, pa0.w+pa1.w);\
            *(uint2*)&As[(buf)*1536 + am*AST + akq] = make_uint2(p2(s.x,s.y), p2(s.z,s.w)); \
            *(uint2*)&Bs[(buf)*4608 + br*BST + bkq] = make_uint2(p2(pb0.x,pb0.y), p2(pb0.z,pb0.w)); \
            *(uint2*)&Bs[(buf)*4608 + (64+br)*BST + bkq] = make_uint2(p2(pb1.x,pb1.y), p2(pb1.z,pb1.w)); \
            *(uint2*)&Bs[(buf)*4608 + (128+br)*BST + bkq] = make_uint2(p2(pb2.x,pb2.y), p2(pb2.z,pb2.w)); \
        } while (0)

        G2_LOAD(0);
        G2_STORE(0);
        __syncthreads();

        #pragma unroll 1
        for (int cch = 0; cch < 16; cch++) {
            const int buf = cch & 1;
            if (cch < 15) G2_LOAD((cch + 1) * 16);
            const unsigned aoff = as_base + (unsigned)buf * 3072u;
            const unsigned boff = bs_base + (unsigned)buf * 9216u;
            unsigned a[2][4], b[3][4];
            #pragma unroll
            for (int mi = 0; mi < 2; mi++) ldmx4(a[mi], aoff + aoffs + mi*768u);
            #pragma unroll
            for (int np = 0; np < 3; np++) ldmx4(b[np], boff + boffs + np*768u);
            #pragma unroll
            for (int mi = 0; mi < 2; mi++)
                #pragma unroll
                for (int ni = 0; ni < 6; ni++)
                    mma16816(c_[mi][ni], a[mi], b[ni>>1][ni&1], b[ni>>1][(ni&1)+2]);
            if (cch < 15) G2_STORE(buf ^ 1);
            __syncthreads();
        }

        #pragma unroll
        for (int mi = 0; mi < 2; mi++) {
            #pragma unroll
            for (int ni = 0; ni < 6; ni++) {
                const int jc = nw + ni*8 + 2*t;
                const int r0 = mw + mi*16 + g;
                const float* cr = c_[mi][ni];
                float b0, b1;
                if (jc < 128) { b0 = boff2[jc]; b1 = boff2[jc+1]; }
                else          { b0 = battn[jc-128]; b1 = battn[jc-127]; }
                int mr0 = m0 + r0, mr1 = mr0 + 8;
                if (mr0 < MROWS)
                    *(float2*)&d_offattn[(size_t)mr0*OAC + jc] = make_float2(cr[0]+b0, cr[1]+b1);
                if (mr1 < MROWS)
                    *(float2*)&d_offattn[(size_t)mr1*OAC + jc] = make_float2(cr[2]+b0, cr[3]+b1);
            }
        }
        #undef G2_LOAD
        #undef G2_STORE
    } else {
        // ================= GEMM1 body: value GEMM, tile 128x64 =================
        __half* As = (__half*)smraw;              // 2 bufs x 3072 halves (6144B each)
        __half* Bs = (__half*)(smraw + 12288);    // 2 bufs x 1536 halves (3072B each)
        const int idx = blockIdx.x - G2_BLOCKS;   // 0..527
        const int j0 = (idx & 3) * 64;
        const int bm = idx >> 2;                  // 0..131
        const int camI = bm / 22, p0 = (bm % 22) * 128;
        const int mw = (wid & 3) * 32, nw = (wid >> 2) * 32;

        const int bn_ = tid >> 2, bkq = (tid & 3) * 4;
        const float* wrow = Wv + (size_t)(j0 + bn_)*DIM;
        const int kk = tid >> 4, pg = tid & 15;

        const unsigned as_base = smem_addr(As);
        const unsigned bs_base = smem_addr(Bs);
        const unsigned atoffs = (unsigned)((((lane & 7) + bit4*8) * MSTR + mw + bit3*8) << 1);
        const unsigned boffs = (unsigned)(((nw + (lane & 7) + bit3*8) * BST + bit4*8) << 1);

        float c_[2][4][4];
        #pragma unroll
        for (int mi = 0; mi < 2; mi++)
            #pragma unroll
            for (int ni = 0; ni < 4; ni++)
                #pragma unroll
                for (int r = 0; r < 4; r++) c_[mi][ni][r] = 0.f;

        float4 pa0, pa1, pb;
        #define G1_LOAD(k0) do {                                                      \
            const float* src = feat + ((size_t)(camI*DIM + (k0) + kk))*HWF + p0 + pg*8;\
            pa0 = *(const float4*)src; pa1 = *(const float4*)(src + 4);               \
            pb = *(const float4*)(wrow + (k0) + bkq);                                 \
        } while (0)
        #define G1_STORE(buf) do {                                                    \
            uint4 ha = make_uint4(p2(pa0.x,pa0.y), p2(pa0.z,pa0.w),                   \
                                  p2(pa1.x,pa1.y), p2(pa1.z,pa1.w));                  \
            *(uint4*)&As[(buf)*3072 + kk*MSTR + pg*8] = ha;                           \
            *(uint2*)&Bs[(buf)*1536 + bn_*BST + bkq] = make_uint2(p2(pb.x,pb.y), p2(pb.z,pb.w)); \
        } while (0)

        G1_LOAD(0);
        G1_STORE(0);
        __syncthreads();

        #pragma unroll 1
        for (int cch = 0; cch < 16; cch++) {
            const int buf = cch & 1;
            if (cch < 15) G1_LOAD((cch + 1) * 16);
            const unsigned aoff = as_base + (unsigned)buf * 6144u;
            const unsigned boff = bs_base + (unsigned)buf * 3072u;
            unsigned a[2][4], b[2][4];
            #pragma unroll
            for (int mi = 0; mi < 2; mi++) ldmx4t(a[mi], aoff + atoffs + mi*32u);
            #pragma unroll
            for (int np = 0; np < 2; np++) ldmx4(b[np], boff + boffs + np*768u);
            #pragma unroll
            for (int mi = 0; mi < 2; mi++) {
                mma16816(c_[mi][0], a[mi], b[0][0], b[0][2]);
                mma16816(c_[mi][1], a[mi], b[0][1], b[0][3]);
                mma16816(c_[mi][2], a[mi], b[1][0], b[1][2]);
                mma16816(c_[mi][3], a[mi], b[1][1], b[1][3]);
            }
            if (cch < 15) G1_STORE(buf ^ 1);
            __syncthreads();
        }

        #pragma unroll
        for (int mi = 0; mi < 2; mi++) {
            #pragma unroll
            for (int ni = 0; ni < 4; ni++) {
                const int jc = j0 + nw + ni*8 + 2*t;
                const int r0 = mw + mi*16 + g;
                const float* cr = c_[mi][ni];
                const int h = jc >> 5, hd = jc & 31;
                float b0 = d_bias2[camI*DIM + jc], b1 = d_bias2[camI*DIM + jc + 1];
                __half* o0 = d_value + ((size_t)(camI*NH + h)*HWF + p0 + r0)*HD + hd;
                __half* o1 = o0 + 8*HD;
                *(__half2*)o0 = __floats2half2_rn(cr[0] + b0, cr[1] + b1);
                *(__half2*)o1 = __floats2half2_rn(cr[2] + b0, cr[3] + b1);
            }
        }
        #undef G1_LOAD
        #undef G1_STORE
    }
}

// ---------------- GEMM3: final (tile 128x64, A = d_S) ----------------
__global__ __launch_bounds__(256, 2) void gemm3_tc(
    const float* __restrict__ bias0, float* __restrict__ C)
{
    __shared__ __half As[2][3072];
    __shared__ __half Bs[2][1536];
    const int tid = threadIdx.x;
    const int lane = tid & 31, wid = tid >> 5;
    const int mw = (wid & 3) * 32, nw = (wid >> 2) * 32;
    const int g = lane >> 2, t = lane & 3;
    const int j0 = blockIdx.x * 64;
    const int m0 = blockIdx.y * 128;

    const int bn_ = tid >> 2, bkq = (tid & 3) * 4;
    const float* wrow = (const float*)d_Wc + (size_t)(j0 + bn_)*DIM;
    const int am = tid >> 1, akq = (tid & 1) * 8;
    const int mga = m0 + am;

    const unsigned as_base = smem_addr(&As[0][0]);
    const unsigned bs_base = smem_addr(&Bs[0][0]);
    const int bit3 = (lane >> 3) & 1, bit4 = lane >> 4;
    const unsigned aoffs = (unsigned)(((mw + (lane & 7) + bit3*8) * AST + bit4*8) << 1);
    const unsigned boffs = (unsigned)(((nw + (lane & 7) + bit3*8) * BST + bit4*8) << 1);

    float c_[2][4][4];
    #pragma unroll
    for (int mi = 0; mi < 2; mi++)
        #pragma unroll
        for (int ni = 0; ni < 4; ni++)
            #pragma unroll
            for (int r = 0; r < 4; r++) c_[mi][ni][r] = 0.f;

    float4 pa0, pa1, pb;
    auto zero4 = make_float4(0.f, 0.f, 0.f, 0.f);
    #define G3_LOAD(k0) do {                                                      \
        pa0 = zero4; pa1 = zero4;                                                 \
        if (mga < QN) {                                                           \
            pa0 = *(const float4*)((const float*)d_S + (size_t)mga*DIM + (k0) + akq);     \
            pa1 = *(const float4*)((const float*)d_S + (size_t)mga*DIM + (k0) + akq + 4); \
        }                                                                         \
        pb = *(const float4*)(wrow + (k0) + bkq);                                 \
    } while (0)
    #define G3_STORE(buf) do {                                                    \
        uint4 ha = make_uint4(p2(pa0.x,pa0.y), p2(pa0.z,pa0.w),                   \
                              p2(pa1.x,pa1.y), p2(pa1.z,pa1.w));                  \
        *(uint4*)&As[buf][am*AST + akq] = ha;                                     \
        *(uint2*)&Bs[buf][bn_*BST + bkq] = make_uint2(p2(pb.x,pb.y), p2(pb.z,pb.w)); \
    } while (0)

    G3_LOAD(0);
    G3_STORE(0);
    __syncthreads();

    #pragma unroll 1
    for (int cch = 0; cch < 16; cch++) {
        const int buf = cch & 1;
        if (cch < 15) G3_LOAD((cch + 1) * 16);
        const unsigned aoff = as_base + (unsigned)buf * 6144u;
        const unsigned boff = bs_base + (unsigned)buf * 3072u;
        unsigned a[2][4], b[2][4];
        #pragma unroll
        for (int mi = 0; mi < 2; mi++) ldmx4(a[mi], aoff + aoffs + mi*768u);
        #pragma unroll
        for (int np = 0; np < 2; np++) ldmx4(b[np], boff + boffs + np*768u);
        #pragma unroll
        for (int mi = 0; mi < 2; mi++) {
            mma16816(c_[mi][0], a[mi], b[0][0], b[0][2]);
            mma16816(c_[mi][1], a[mi], b[0][1], b[0][3]);
            mma16816(c_[mi][2], a[mi], b[1][0], b[1][2]);
            mma16816(c_[mi][3], a[mi], b[1][1], b[1][3]);
        }
        if (cch < 15) G3_STORE(buf ^ 1);
        __syncthreads();
    }

    #pragma unroll
    for (int mi = 0; mi < 2; mi++) {
        #pragma unroll
        for (int ni = 0; ni < 4; ni++) {
            const int jc = j0 + nw + ni*8 + 2*t;
            const int r0 = mw + mi*16 + g;
            const float* cr = c_[mi][ni];
            float b0 = bias0[jc] , b1 = bias0[jc+1];
            float e0 = d_bi2[jc], e1 = d_bi2[jc+1];
            int mr0 = m0 + r0, mr1 = mr0 + 8;
            if (mr0 < QN) {
                float gf = d_gflag[mr0];
                *(float2*)&C[(size_t)mr0*DIM + jc] =
                    make_float2(cr[0] + b0 + gf*e0, cr[1] + b1 + gf*e1);
            }
            if (mr1 < QN) {
                float gf = d_gflag[mr1];
                *(float2*)&C[(size_t)mr1*DIM + jc] =
                    make_float2(cr[2] + b0 + gf*e0, cr[3] + b1 + gf*e1);
            }
        }
    }
    #undef G3_LOAD
    #undef G3_STORE
}

// ---------------- sampling v3: 16B gathers, 2 points/iter ----------------
__global__ __launch_bounds__(256) void sample_kernel(const float* __restrict__ ref,
                                                     const void* __restrict__ mask) {
    const int q = blockIdx.x;
    const int tid = threadIdx.x;
    const int h = tid>>5, l = tid&31;
    const int c8 = l&7;
    const int ox = (l>>3)&1, oy = l>>4;
    const int oct = l&3, corg = (l>>2)&3, psel = l>>4;
    const int oxg = corg&1, oyg = corg>>1;
    const int srcl_base = oyg*16 + oxg*8 + psel;
    __shared__ float s_hit[NCAM];
    __shared__ float s_inv, s_g;
    if (tid < NCAM) {
        const int mode = d_mask_mode;
        size_t base = (size_t)(tid*QN + q)*8;
        int hit = mask_elem(mask, base+0, mode) | mask_elem(mask, base+2, mode) |
                  mask_elem(mask, base+4, mode) | mask_elem(mask, base+6, mode);
        s_hit[tid] = hit ? 1.f : 0.f;
    }
    __syncthreads();
    if (tid == 0) {
        float c = s_hit[0]+s_hit[1]+s_hit[2]+s_hit[3]+s_hit[4]+s_hit[5];
        s_g = (c > 0.f) ? 1.f : 0.f;
        s_inv = 1.f / fmaxf(c, 1.f);
    }
    __syncthreads();
    float acc[8];
    #pragma unroll
    for (int i = 0; i < 8; i++) acc[i] = 0.f;

    for (int camI = 0; camI < NCAM; camI++) {
        if (s_hit[camI] == 0.f) continue;
        const float* row = d_offattn + (size_t)(camI*QN + q)*OAC;
        float logit = row[128 + h*8 + c8];
        float2 of = *(const float2*)(row + h*16 + c8*2);
        const float* rp = ref + ((size_t)(camI*QN + q)*4 + (c8&3))*2;
        float rx = rp[0], ry = rp[1];
        float e = __expf(logit);
        float sm = e;
        sm += __shfl_xor_sync(0xffffffffu, sm, 1, 8);
        sm += __shfl_xor_sync(0xffffffffu, sm, 2, 8);
        sm += __shfl_xor_sync(0xffffffffu, sm, 4, 8);
        float w = __fdividef(e, sm);
        float x = fmaf(rx, (float)WFv, of.x) - 0.5f;
        float y = fmaf(ry, (float)HFv, of.y) - 0.5f;
        float xf = floorf(x), yf = floorf(y);
        float dx = x - xf, dy = y - yf;
        int xi = (int)xf + ox;
        int yi = (int)yf + oy;
        float wx = ox ? dx : (1.f - dx);
        float wy = oy ? dy : (1.f - dy);
        bool valid = (xi >= 0) && (xi < WFv) && (yi >= 0) && (yi < HFv);
        float wc = valid ? (w*wx*wy) : 0.f;
        int pix = min(max(yi,0),HFv-1)*WFv + min(max(xi,0),WFv-1);
        const __half* vh = d_value + (size_t)(camI*NH + h)*HWF*HD + oct*8;
        #pragma unroll
        for (int pp = 0; pp < 4; pp++) {
            int srcl = srcl_base + 2*pp;
            float wcp = __shfl_sync(0xffffffffu, wc,  srcl);
            int  pixp = __shfl_sync(0xffffffffu, pix, srcl);
            uint4 raw = *(const uint4*)(vh + (size_t)pixp*HD);
            float2 f0 = __half22float2(*(__half2*)&raw.x);
            float2 f1 = __half22float2(*(__half2*)&raw.y);
            float2 f2 = __half22float2(*(__half2*)&raw.z);
            float2 f3 = __half22float2(*(__half2*)&raw.w);
            acc[0] = fmaf(wcp, f0.x, acc[0]); acc[1] = fmaf(wcp, f0.y, acc[1]);
            acc[2] = fmaf(wcp, f1.x, acc[2]); acc[3] = fmaf(wcp, f1.y, acc[3]);
            acc[4] = fmaf(wcp, f2.x, acc[4]); acc[5] = fmaf(wcp, f2.y, acc[5]);
            acc[6] = fmaf(wcp, f3.x, acc[6]); acc[7] = fmaf(wcp, f3.y, acc[7]);
        }
    }
    #pragma unroll
    for (int i = 0; i < 8; i++) {
        acc[i] += __shfl_xor_sync(0xffffffffu, acc[i], 4);
        acc[i] += __shfl_xor_sync(0xffffffffu, acc[i], 8);
        acc[i] += __shfl_xor_sync(0xffffffffu, acc[i], 16);
    }
    if (l < 4) {
        float inv = s_inv;
        float* o = d_S + (size_t)q*DIM + h*HD + l*8;
        *(float4*)o       = make_float4(acc[0]*inv, acc[1]*inv, acc[2]*inv, acc[3]*inv);
        *(float4*)(o + 4) = make_float4(acc[4]*inv, acc[5]*inv, acc[6]*inv, acc[7]*inv);
    }
    if (tid == 0) d_gflag[q] = s_g;
}

// ---------------- launch ----------------
extern "C" void kernel_launch(void* const* d_in, const int* in_sizes, int n_in,
                              void* d_out, int out_size) {
    const float* queries = (const float*)d_in[0];
    const float* pos     = (const float*)d_in[1];
    const float* lvl     = (const float*)d_in[2];
    const float* camemb  = (const float*)d_in[3];
    const float* feat    = (const float*)d_in[4];
    const float* ref     = (const float*)d_in[5];
    const void*  mask    = (const void*)d_in[6];
    const float* W_value = (const float*)d_in[7];
    const float* b_value = (const float*)d_in[8];
    const float* W_off   = (const float*)d_in[9];
    const float* b_off   = (const float*)d_in[10];
    const float* W_attn  = (const float*)d_in[11];
    const float* b_attn  = (const float*)d_in[12];
    const float* W_inner = (const float*)d_in[13];
    const float* b_inner = (const float*)d_in[14];
    const float* W_out   = (const float*)d_in[15];
    const float* b_out   = (const float*)d_in[16];
    float* out = (float*)d_out;

    prep_a<<<NCAM + 1, DIM>>>(lvl, camemb, W_value, b_value, (const unsigned int*)mask);
    prep_b<<<DIM + 1, DIM>>>(W_out, W_inner, b_inner);
    fat_gemm<<<G2_BLOCKS + 528, 256>>>(feat, W_value, queries, pos,
                                       W_off, W_attn, b_off, b_attn);
    sample_kernel<<<QN, 256>>>(ref, mask);
    gemm3_tc<<<dim3(4, 79), 256>>>(b_out, out);
    (void)in_sizes; (void)n_in; (void)out_size;
}